// round 6
// baseline (speedup 1.0000x reference)
#include <cuda_runtime.h>
#include <cuda_fp16.h>
#include <cstdint>
#include <cstddef>

#define EPSF 1e-5f
constexpr int BB = 32, F0 = 20, T0 = 2048;
constexpr int T1 = 2044, T2 = 2040, T3 = 2034, T5 = 2034;
constexpr int C5 = 1500, C5P = 1536, NS = 256;

// ------------------------------- scratch -----------------------------------
__device__ __align__(16) __half g_xhi[(size_t)BB * T0 * 32],  g_xlo[(size_t)BB * T0 * 32];
__device__ __align__(16) __half g_a1hi[(size_t)BB * T1 * 512], g_a1lo[(size_t)BB * T1 * 512];
__device__ __align__(16) __half g_a2hi[(size_t)BB * T2 * 512], g_a2lo[(size_t)BB * T2 * 512];
__device__ __align__(16) __half g_a3hi[(size_t)BB * T3 * 512], g_a3lo[(size_t)BB * T3 * 512];
__device__ __align__(16) __half g_a4hi[(size_t)BB * T3 * 512], g_a4lo[(size_t)BB * T3 * 512];
__device__ __align__(16) __half g_w1hi[512 * 160],  g_w1lo[512 * 160];
__device__ __align__(16) __half g_w2hi[512 * 1536], g_w2lo[512 * 1536];
__device__ __align__(16) __half g_w3hi[512 * 1536], g_w3lo[512 * 1536];
__device__ __align__(16) __half g_w4hi[512 * 512],  g_w4lo[512 * 512];
__device__ __align__(16) __half g_w5hi[C5P * 512],  g_w5lo[C5P * 512];
__device__ float g_b1p[512], g_b2p[512], g_b3p[512], g_b4p[512], g_b5p[C5P];
__device__ float g_ps[NS * 512], g_pq[NS * 512];
__device__ float g_p5s[16 * BB * C5P], g_p5q[16 * BB * C5P];
__device__ float g_m1[512], g_i1[512], g_m2[512], g_i2[512];
__device__ float g_m3[512], g_i3[512], g_m4[512], g_i4[512];
__device__ float g_m5[C5], g_i5[C5];
__device__ float g_rsum[BB * C5], g_rsq[BB * C5];
__device__ float g_pool[BB * 3000];
__device__ float g_z1[BB * 512], g_u1[BB * 512], g_z2[BB * 512];

// ----------------------------- helpers --------------------------------------
__device__ __forceinline__ uint32_t s2u(const void* p) {
    uint32_t a;
    asm("{ .reg .u64 t; cvta.to.shared.u64 t, %1; cvt.u32.u64 %0, t; }" : "=r"(a) : "l"(p));
    return a;
}
__device__ __forceinline__ void ldm_x4(uint32_t a[4], uint32_t addr) {
    asm volatile("ldmatrix.sync.aligned.m8n8.x4.shared.b16 {%0,%1,%2,%3}, [%4];"
                 : "=r"(a[0]), "=r"(a[1]), "=r"(a[2]), "=r"(a[3]) : "r"(addr));
}
__device__ __forceinline__ void mma16816(float c[4], const uint32_t a[4], const uint32_t b[2]) {
    asm volatile("mma.sync.aligned.m16n8k16.row.col.f32.f16.f16.f32 "
                 "{%0,%1,%2,%3}, {%4,%5,%6,%7}, {%8,%9}, {%0,%1,%2,%3};"
                 : "+f"(c[0]), "+f"(c[1]), "+f"(c[2]), "+f"(c[3])
                 : "r"(a[0]), "r"(a[1]), "r"(a[2]), "r"(a[3]), "r"(b[0]), "r"(b[1]));
}
__device__ __forceinline__ void cpa16(uint32_t dst, const void* src, int sz) {
    asm volatile("cp.async.ca.shared.global [%0], [%1], 16, %2;" :: "r"(dst), "l"(src), "r"(sz));
}
#define CP_COMMIT() asm volatile("cp.async.commit_group;" ::: "memory")
#define CP_WAIT2() asm volatile("cp.async.wait_group 2;" ::: "memory")

// ------------------------------ prep kernels --------------------------------
__global__ void xsplit(const float* __restrict__ x, __half* __restrict__ xh, __half* __restrict__ xl) {
    int idx = blockIdx.x * 256 + threadIdx.x;
    if (idx >= BB * T0 * 32) return;
    int f = idx & 31, bt = idx >> 5;
    float v = (f < F0) ? x[(size_t)bt * F0 + f] : 0.f;
    __half h = __float2half(v);
    xh[idx] = h;
    xl[idx] = __float2half(v - __half2float(h));
}

__global__ void fold_split(const float* __restrict__ w, const float* __restrict__ bias,
                           const float* __restrict__ mean, const float* __restrict__ istd,
                           const float* __restrict__ g, const float* __restrict__ be,
                           __half* __restrict__ wh, __half* __restrict__ wl, float* __restrict__ bp,
                           int Korig, int NOFF, int C, int Cpad, int Cout, int Kp) {
    int o = blockIdx.x;
    float part = 0.f;
    for (int k = threadIdx.x; k < Kp; k += 256) {
        int j = k / Cpad, c = k - j * Cpad;
        float wa = 0.f;
        if (o < Cout && c < C) {
            float a = 1.f, d = 0.f;
            if (mean) { a = istd[c] * (g ? g[c] : 1.f); d = (be ? be[c] : 0.f) - mean[c] * a; }
            float wv = w[(size_t)o * Korig + c * NOFF + j];
            wa = wv * a;
            part += wv * d;
        }
        __half h = __float2half(wa);
        wh[(size_t)o * Kp + k] = h;
        wl[(size_t)o * Kp + k] = __float2half(wa - __half2float(h));
    }
    __shared__ float sh[256];
    sh[threadIdx.x] = part;
    __syncthreads();
    for (int d2 = 128; d2 > 0; d2 >>= 1) {
        if (threadIdx.x < d2) sh[threadIdx.x] += sh[threadIdx.x + d2];
        __syncthreads();
    }
    if (threadIdx.x == 0) bp[o] = (o < Cout ? bias[o] : 0.f) + sh[0];
}

// -------------------------- mma.sync GEMM -----------------------------------
// CTA 128x128, BK=32, 8 warps (4m x 2n), warp 32x64, fp16 hi/lo 3-term.
// 3-stage cp.async pipeline; stage = 40960B.
// Normal mode: write Oh/Ol activations. Stats mode (P5s!=0): per-CTA column
// (sum,sumsq) partials -> P5s/P5q[bx][b][col], activations not materialized.
__global__ __launch_bounds__(256)
void mma_gemm(const __half* __restrict__ Ah, const __half* __restrict__ Al,
              const __half* __restrict__ Wh, const __half* __restrict__ Wl,
              const float* __restrict__ bias,
              __half* __restrict__ Oh, __half* __restrict__ Ol,
              float* __restrict__ P5s, float* __restrict__ P5q,
              int Tin, int Tout, int Cpad, int step, int Kp, int Coutp, int act) {
    extern __shared__ char smem[];
    uint32_t su = s2u(smem);
    int tid = threadIdx.x, lane = tid & 31, wid = tid >> 5;
    int b = blockIdx.z, t0 = blockIdx.x * 128, obase = blockIdx.y * 128;
    int wm = wid >> 1, wn = wid & 1;
    int nk = Kp >> 5;

    float acc[2][8][4];
#pragma unroll
    for (int i = 0; i < 2; i++)
#pragma unroll
        for (int j = 0; j < 8; j++)
#pragma unroll
            for (int q = 0; q < 4; q++) acc[i][j][q] = 0.f;

    auto load_stage = [&](int buf, int kc) {
        int kc0 = kc << 5;
        int j = kc0 / Cpad, c0 = kc0 - j * Cpad, off = j * step;
        uint32_t sb = su + buf * 40960;
        const __half* pa[2] = {Ah, Al};
        const __half* pw[2] = {Wh, Wl};
#pragma unroll
        for (int h = 0; h < 2; h++) {
#pragma unroll
            for (int i = 0; i < 2; i++) {
                int e = tid + i * 256, r = e >> 2, c = e & 3;
                cpa16(sb + h * 10240 + r * 80 + c * 16,
                      pa[h] + ((size_t)b * Tin + t0 + off + r) * Cpad + c0 + c * 8,
                      (t0 + r < Tout) ? 16 : 0);
            }
#pragma unroll
            for (int i = 0; i < 2; i++) {
                int e = tid + i * 256, r = e >> 2, c = e & 3;
                cpa16(sb + 20480 + h * 10240 + r * 80 + c * 16,
                      pw[h] + ((size_t)(obase + r)) * Kp + kc0 + c * 8, 16);
            }
        }
        CP_COMMIT();
    };

    auto compute = [&](int buf) {
        uint32_t sb = su + buf * 40960;
#pragma unroll
        for (int ks = 0; ks < 2; ks++) {
            uint32_t ah[2][4], al[2][4];
#pragma unroll
            for (int mf = 0; mf < 2; mf++) {
                int row = wm * 32 + mf * 16 + (lane & 15);
                uint32_t addr = sb + row * 80 + (ks * 16 + ((lane >> 4) << 3)) * 2;
                ldm_x4(ah[mf], addr);
                ldm_x4(al[mf], addr + 10240);
            }
#pragma unroll
            for (int nb = 0; nb < 2; nb++) {
                uint32_t bh[4][2], bl[4][2];
#pragma unroll
                for (int qq = 0; qq < 2; qq++) {
                    int g = lane >> 3;
                    int rowb = wn * 64 + nb * 32 + qq * 16 + ((g >> 1) << 3) + (lane & 7);
                    uint32_t addr = sb + 20480 + rowb * 80 + (ks * 16 + ((g & 1) << 3)) * 2;
                    uint32_t th[4], tl[4];
                    ldm_x4(th, addr);
                    ldm_x4(tl, addr + 10240);
                    bh[qq * 2][0] = th[0]; bh[qq * 2][1] = th[1];
                    bh[qq * 2 + 1][0] = th[2]; bh[qq * 2 + 1][1] = th[3];
                    bl[qq * 2][0] = tl[0]; bl[qq * 2][1] = tl[1];
                    bl[qq * 2 + 1][0] = tl[2]; bl[qq * 2 + 1][1] = tl[3];
                }
#pragma unroll
                for (int mf = 0; mf < 2; mf++)
#pragma unroll
                    for (int q = 0; q < 4; q++) {
                        int nf = nb * 4 + q;
                        mma16816(acc[mf][nf], ah[mf], bh[q]);
                        mma16816(acc[mf][nf], ah[mf], bl[q]);
                        mma16816(acc[mf][nf], al[mf], bh[q]);
                    }
            }
        }
    };

    load_stage(0, 0);
    load_stage(1, 1);
    load_stage(2, 2);
    for (int kc = 0; kc < nk; kc++) {
        CP_WAIT2();
        __syncthreads();
        compute(kc % 3);
        __syncthreads();
        if (kc + 3 < nk) load_stage(kc % 3, kc + 3);
        else CP_COMMIT();
    }

    int l4 = lane >> 2, l2 = (lane & 3) << 1;
    if (!P5s) {
#pragma unroll
        for (int mf = 0; mf < 2; mf++)
#pragma unroll
            for (int hh = 0; hh < 2; hh++) {
                int t = t0 + wm * 32 + mf * 16 + l4 + hh * 8;
                if (t >= Tout) continue;
                size_t ro = ((size_t)b * Tout + t) * Coutp + obase + wn * 64;
#pragma unroll
                for (int nf = 0; nf < 8; nf++) {
                    int o = nf * 8 + l2;
                    float v0 = acc[mf][nf][hh * 2 + 0] + bias[obase + wn * 64 + o];
                    float v1 = acc[mf][nf][hh * 2 + 1] + bias[obase + wn * 64 + o + 1];
                    v0 = fmaxf(v0, 0.f); v1 = fmaxf(v1, 0.f);
                    if (act) { v0 = fminf(v0, 6.f); v1 = fminf(v1, 6.f); }
                    __half h0 = __float2half(v0), h1 = __float2half(v1);
                    *(__half2*)(Oh + ro + o) = __halves2half2(h0, h1);
                    *(__half2*)(Ol + ro + o) = __halves2half2(
                        __float2half(v0 - __half2float(h0)), __float2half(v1 - __half2float(h1)));
                }
            }
    } else {
        // stats mode: column (sum, sumsq) over this CTA's valid t rows
        float s_[8][2] = {}, q_[8][2] = {};
#pragma unroll
        for (int mf = 0; mf < 2; mf++)
#pragma unroll
            for (int hh = 0; hh < 2; hh++) {
                int t = t0 + wm * 32 + mf * 16 + l4 + hh * 8;
                bool tv = t < Tout;
#pragma unroll
                for (int nf = 0; nf < 8; nf++)
#pragma unroll
                    for (int e = 0; e < 2; e++) {
                        float v = acc[mf][nf][hh * 2 + e] + bias[obase + wn * 64 + nf * 8 + l2 + e];
                        v = fminf(fmaxf(v, 0.f), 6.f);
                        if (tv) { s_[nf][e] += v; q_[nf][e] += v * v; }
                    }
            }
#pragma unroll
        for (int nf = 0; nf < 8; nf++)
#pragma unroll
            for (int e = 0; e < 2; e++)
#pragma unroll
                for (int o = 4; o <= 16; o <<= 1) {
                    s_[nf][e] += __shfl_xor_sync(0xffffffffu, s_[nf][e], o);
                    q_[nf][e] += __shfl_xor_sync(0xffffffffu, q_[nf][e], o);
                }
        float* ss = (float*)smem;
        float* sq = ss + 128;
        __syncthreads();
        if (tid < 256) ss[tid] = 0.f;   // zeros both ss[0..127] and sq[0..127]
        __syncthreads();
        if ((lane >> 2) == 0) {
#pragma unroll
            for (int nf = 0; nf < 8; nf++)
#pragma unroll
                for (int e = 0; e < 2; e++) {
                    int col = wn * 64 + nf * 8 + (lane & 3) * 2 + e;
                    atomicAdd(&ss[col], s_[nf][e]);
                    atomicAdd(&sq[col], q_[nf][e]);
                }
        }
        __syncthreads();
        if (tid < 128) {
            size_t pidx = ((size_t)blockIdx.x * BB + b) * Coutp + obase + tid;
            P5s[pidx] = ss[tid];
            P5q[pidx] = sq[tid];
        }
    }
}

// --------------------------- stats / tail -----------------------------------
__global__ void statpart(const __half* __restrict__ hi, const __half* __restrict__ lo,
                         float* __restrict__ ps, float* __restrict__ pq, int Mrows, int Cpad) {
    int c2 = blockIdx.x * 256 + threadIdx.x;
    int s = blockIdx.y, ns = gridDim.y;
    int per = (Mrows + ns - 1) / ns;
    int m0 = s * per, m1 = min(m0 + per, Mrows);
    const __half2* H = (const __half2*)hi;
    const __half2* L = (const __half2*)lo;
    int C2 = Cpad >> 1;
    float sx = 0.f, sy = 0.f, qx = 0.f, qy = 0.f;
    for (int m = m0; m < m1; m++) {
        float2 h = __half22float2(H[(size_t)m * C2 + c2]);
        float2 l = __half22float2(L[(size_t)m * C2 + c2]);
        float v0 = h.x + l.x, v1 = h.y + l.y;
        sx += v0; sy += v1; qx += v0 * v0; qy += v1 * v1;
    }
    ps[(size_t)s * Cpad + 2 * c2] = sx;
    ps[(size_t)s * Cpad + 2 * c2 + 1] = sy;
    pq[(size_t)s * Cpad + 2 * c2] = qx;
    pq[(size_t)s * Cpad + 2 * c2 + 1] = qy;
}
__global__ void statfin(const float* __restrict__ ps, const float* __restrict__ pq,
                        float* __restrict__ mean, float* __restrict__ istd, int Cpad, float N) {
    int c = blockIdx.x * 256 + threadIdx.x;
    if (c >= Cpad) return;
    float s = 0.f, q = 0.f;
    for (int i = 0; i < NS; i++) { s += ps[(size_t)i * Cpad + c]; q += pq[(size_t)i * Cpad + c]; }
    float m = s / N;
    mean[c] = m;
    istd[c] = rsqrtf(q / N - m * m + EPSF);
}
__global__ void part5reduce(const float* __restrict__ ps, const float* __restrict__ pq,
                            float* __restrict__ rsum, float* __restrict__ rsq) {
    int c = blockIdx.x * 256 + threadIdx.x;
    int b = blockIdx.y;
    if (c >= C5) return;
    float s = 0.f, q = 0.f;
    for (int i = 0; i < 16; i++) {
        s += ps[((size_t)i * BB + b) * C5P + c];
        q += pq[((size_t)i * BB + b) * C5P + c];
    }
    rsum[b * C5 + c] = s;
    rsq[b * C5 + c] = q;
}
__global__ void chstats5(const float* __restrict__ rsum, const float* __restrict__ rsq,
                         float* __restrict__ mean, float* __restrict__ istd) {
    int c = blockIdx.x * 256 + threadIdx.x;
    if (c >= C5) return;
    float s = 0.f, ss = 0.f;
    for (int b = 0; b < BB; b++) { s += rsum[b * C5 + c]; ss += rsq[b * C5 + c]; }
    float N = (float)BB * (float)T5;
    float m = s / N;
    mean[c] = m;
    istd[c] = rsqrtf(ss / N - m * m + EPSF);
}
__global__ void pool_kernel(const float* __restrict__ rsum, const float* __restrict__ rsq,
                            const float* __restrict__ m5, const float* __restrict__ i5,
                            const float* __restrict__ g5, const float* __restrict__ be5,
                            float* __restrict__ pooled) {
    int idx = blockIdx.x * 256 + threadIdx.x;
    if (idx >= BB * C5) return;
    int c = idx % C5, b = idx / C5;
    float Tf = (float)T5;
    float mt = rsum[b * C5 + c] / Tf;
    float vart = (rsq[b * C5 + c] - Tf * mt * mt) / (Tf - 1.f);
    float a = i5[c] * g5[c];
    float d = be5[c] - m5[c] * a;
    pooled[(size_t)b * 3000 + c] = a * mt + d;
    pooled[(size_t)b * 3000 + 1500 + c] = fabsf(a) * sqrtf(fmaxf(vart, 0.f));
}
__global__ void fc_kernel(const float* __restrict__ in, const float* __restrict__ w,
                          const float* __restrict__ bias, float* __restrict__ out, int K, int Cout) {
    int o = blockIdx.x, b = blockIdx.y;
    const float* ir = in + (size_t)b * K;
    const float* wr = w + (size_t)o * K;
    float s = 0.f;
    for (int k = threadIdx.x; k < K; k += 128) s += ir[k] * wr[k];
    __shared__ float sh[128];
    sh[threadIdx.x] = s;
    __syncthreads();
    for (int d = 64; d > 0; d >>= 1) {
        if (threadIdx.x < d) sh[threadIdx.x] += sh[threadIdx.x + d];
        __syncthreads();
    }
    if (threadIdx.x == 0) out[(size_t)b * Cout + o] = fminf(fmaxf(sh[0] + bias[o], 0.f), 6.f);
}
__global__ void bnc_kernel(const float* __restrict__ z, const float* __restrict__ g,
                           const float* __restrict__ be, float* __restrict__ out, int C) {
    int c = threadIdx.x + blockIdx.x * 256;
    if (c >= C) return;
    float s = 0.f, ss = 0.f;
    for (int b = 0; b < BB; b++) { float v = z[(size_t)b * C + c]; s += v; ss += v * v; }
    float m = s / (float)BB;
    float is = rsqrtf(ss / (float)BB - m * m + EPSF);
    for (int b = 0; b < BB; b++)
        out[(size_t)b * C + c] = (z[(size_t)b * C + c] - m) * is * g[c] + be[c];
}

// ------------------------------- host ---------------------------------------
static void* sa(const void* sym) { void* p = nullptr; cudaGetSymbolAddress(&p, sym); return p; }

extern "C" void kernel_launch(void* const* d_in, const int* in_sizes, int n_in,
                              void* d_out, int out_size) {
    const float* x = (const float*)d_in[0];
    const float *h1w = (const float*)d_in[1], *h1b = (const float*)d_in[2];
    const float *h2w = (const float*)d_in[3], *h2b = (const float*)d_in[4];
    const float *bn2g = (const float*)d_in[5], *bn2b = (const float*)d_in[6];
    const float *h3w = (const float*)d_in[7], *h3b = (const float*)d_in[8];
    const float *bn3g = (const float*)d_in[9], *bn3b = (const float*)d_in[10];
    const float *h4w = (const float*)d_in[11], *h4b = (const float*)d_in[12];
    const float *bn4g = (const float*)d_in[13], *bn4b = (const float*)d_in[14];
    const float *h5w = (const float*)d_in[15], *h5b = (const float*)d_in[16];
    const float *bn5g = (const float*)d_in[17], *bn5b = (const float*)d_in[18];
    const float *l1w = (const float*)d_in[19], *l1b = (const float*)d_in[20];
    const float *bn6g = (const float*)d_in[21], *bn6b = (const float*)d_in[22];
    const float *l2w = (const float*)d_in[23], *l2b = (const float*)d_in[24];
    const float *bn7g = (const float*)d_in[25], *bn7b = (const float*)d_in[26];

    __half *xh = (__half*)sa(g_xhi), *xl = (__half*)sa(g_xlo);
    __half *a1h = (__half*)sa(g_a1hi), *a1l = (__half*)sa(g_a1lo);
    __half *a2h = (__half*)sa(g_a2hi), *a2l = (__half*)sa(g_a2lo);
    __half *a3h = (__half*)sa(g_a3hi), *a3l = (__half*)sa(g_a3lo);
    __half *a4h = (__half*)sa(g_a4hi), *a4l = (__half*)sa(g_a4lo);
    __half *w1h = (__half*)sa(g_w1hi), *w1l = (__half*)sa(g_w1lo);
    __half *w2h = (__half*)sa(g_w2hi), *w2l = (__half*)sa(g_w2lo);
    __half *w3h = (__half*)sa(g_w3hi), *w3l = (__half*)sa(g_w3lo);
    __half *w4h = (__half*)sa(g_w4hi), *w4l = (__half*)sa(g_w4lo);
    __half *w5h = (__half*)sa(g_w5hi), *w5l = (__half*)sa(g_w5lo);
    float *b1 = (float*)sa(g_b1p), *b2 = (float*)sa(g_b2p), *b3 = (float*)sa(g_b3p);
    float *b4 = (float*)sa(g_b4p), *b5 = (float*)sa(g_b5p);
    float *ps = (float*)sa(g_ps), *pq = (float*)sa(g_pq);
    float *p5s = (float*)sa(g_p5s), *p5q = (float*)sa(g_p5q);
    float *m1 = (float*)sa(g_m1), *i1 = (float*)sa(g_i1), *m2 = (float*)sa(g_m2), *i2 = (float*)sa(g_i2);
    float *m3 = (float*)sa(g_m3), *i3 = (float*)sa(g_i3), *m4 = (float*)sa(g_m4), *i4 = (float*)sa(g_i4);
    float *m5 = (float*)sa(g_m5), *i5 = (float*)sa(g_i5);
    float *rsum = (float*)sa(g_rsum), *rsq = (float*)sa(g_rsq), *pool = (float*)sa(g_pool);
    float *z1 = (float*)sa(g_z1), *u1 = (float*)sa(g_u1), *z2 = (float*)sa(g_z2);

    const int SMEMB = 3 * 40960;
    cudaFuncSetAttribute(mma_gemm, cudaFuncAttributeMaxDynamicSharedMemorySize, SMEMB);

    xsplit<<<(BB * T0 * 32 + 255) / 256, 256>>>(x, xh, xl);

    // L1: K'=160 (5 offset blocks, Cpad=32), step 1, relu
    fold_split<<<512, 256>>>(h1w, h1b, nullptr, nullptr, nullptr, nullptr, w1h, w1l, b1, 100, 5, 20, 32, 512, 160);
    mma_gemm<<<dim3(16, 4, BB), 256, SMEMB>>>(xh, xl, w1h, w1l, b1, a1h, a1l, nullptr, nullptr, T0, T1, 32, 1, 160, 512, 0);
    statpart<<<dim3(1, NS), 256>>>(a1h, a1l, ps, pq, BB * T1, 512);
    statfin<<<2, 256>>>(ps, pq, m1, i1, 512, (float)BB * (float)T1);

    // L2: fold bn1, offsets {0,2,4}, relu
    fold_split<<<512, 256>>>(h2w, h2b, m1, i1, nullptr, nullptr, w2h, w2l, b2, 1536, 3, 512, 512, 512, 1536);
    mma_gemm<<<dim3(16, 4, BB), 256, SMEMB>>>(a1h, a1l, w2h, w2l, b2, a2h, a2l, nullptr, nullptr, T1, T2, 512, 2, 1536, 512, 0);
    statpart<<<dim3(1, NS), 256>>>(a2h, a2l, ps, pq, BB * T2, 512);
    statfin<<<2, 256>>>(ps, pq, m2, i2, 512, (float)BB * (float)T2);

    // L3: fold bn2, offsets {0,3,6}, relu
    fold_split<<<512, 256>>>(h3w, h3b, m2, i2, bn2g, bn2b, w3h, w3l, b3, 1536, 3, 512, 512, 512, 1536);
    mma_gemm<<<dim3(16, 4, BB), 256, SMEMB>>>(a2h, a2l, w3h, w3l, b3, a3h, a3l, nullptr, nullptr, T2, T3, 512, 3, 1536, 512, 0);
    statpart<<<dim3(1, NS), 256>>>(a3h, a3l, ps, pq, BB * T3, 512);
    statfin<<<2, 256>>>(ps, pq, m3, i3, 512, (float)BB * (float)T3);

    // L4: fold bn3, 512->512, relu6
    fold_split<<<512, 256>>>(h4w, h4b, m3, i3, bn3g, bn3b, w4h, w4l, b4, 512, 1, 512, 512, 512, 512);
    mma_gemm<<<dim3(16, 4, BB), 256, SMEMB>>>(a3h, a3l, w4h, w4l, b4, a4h, a4l, nullptr, nullptr, T3, T3, 512, 0, 512, 512, 1);
    statpart<<<dim3(1, NS), 256>>>(a4h, a4l, ps, pq, BB * T3, 512);
    statfin<<<2, 256>>>(ps, pq, m4, i4, 512, (float)BB * (float)T3);

    // L5: fold bn4, 512->1500 (pad 1536), relu6; stats fused into epilogue
    fold_split<<<C5P, 256>>>(h5w, h5b, m4, i4, bn4g, bn4b, w5h, w5l, b5, 512, 1, 512, 512, C5, 512);
    mma_gemm<<<dim3(16, 12, BB), 256, SMEMB>>>(a4h, a4l, w5h, w5l, b5, nullptr, nullptr, p5s, p5q, T3, T5, 512, 0, 512, C5P, 1);

    // stats pooling (bn5 folded analytically)
    part5reduce<<<dim3(6, BB), 256>>>(p5s, p5q, rsum, rsq);
    chstats5<<<6, 256>>>(rsum, rsq, m5, i5);
    pool_kernel<<<(BB * C5 + 255) / 256, 256>>>(rsum, rsq, m5, i5, bn5g, bn5b, pool);

    // tail FCs
    fc_kernel<<<dim3(512, BB), 128>>>(pool, l1w, l1b, z1, 3000, 512);
    bnc_kernel<<<2, 256>>>(z1, bn6g, bn6b, u1, 512);
    fc_kernel<<<dim3(512, BB), 128>>>(u1, l2w, l2b, z2, 512, 512);
    bnc_kernel<<<2, 256>>>(z2, bn7g, bn7b, (float*)d_out, 512);
}

// round 7
// speedup vs baseline: 1.8137x; 1.8137x over previous
#include <cuda_runtime.h>
#include <cuda_fp16.h>
#include <cstdint>
#include <cstddef>

#define EPSF 1e-5f
constexpr int BB = 32, F0 = 20, T0 = 2048;
constexpr int T1 = 2044, T2 = 2040, T3 = 2034, T5 = 2034;
constexpr int C5 = 1500, C5P = 1536, NS = 256;

// ------------------------------- scratch -----------------------------------
__device__ __align__(16) __half g_xhi[(size_t)BB * T0 * 32],  g_xlo[(size_t)BB * T0 * 32];
__device__ __align__(16) __half g_a1hi[(size_t)BB * T1 * 512], g_a1lo[(size_t)BB * T1 * 512];
__device__ __align__(16) __half g_a2hi[(size_t)BB * T2 * 512], g_a2lo[(size_t)BB * T2 * 512];
__device__ __align__(16) __half g_a3hi[(size_t)BB * T3 * 512], g_a3lo[(size_t)BB * T3 * 512];
__device__ __align__(16) __half g_a4hi[(size_t)BB * T3 * 512], g_a4lo[(size_t)BB * T3 * 512];
__device__ __align__(16) __half g_w1hi[512 * 160],  g_w1lo[512 * 160];
__device__ __align__(16) __half g_w2hi[512 * 1536], g_w2lo[512 * 1536];
__device__ __align__(16) __half g_w3hi[512 * 1536], g_w3lo[512 * 1536];
__device__ __align__(16) __half g_w4hi[512 * 512],  g_w4lo[512 * 512];
__device__ __align__(16) __half g_w5hi[C5P * 512],  g_w5lo[C5P * 512];
__device__ float g_b1p[512], g_b2p[512], g_b3p[512], g_b4p[512], g_b5p[C5P];
__device__ float g_ps[NS * 512], g_pq[NS * 512];
__device__ float g_p5s[16 * BB * C5P], g_p5q[16 * BB * C5P];
__device__ float g_m1[512], g_i1[512], g_m2[512], g_i2[512];
__device__ float g_m3[512], g_i3[512], g_m4[512], g_i4[512];
__device__ float g_m5[C5], g_i5[C5];
__device__ float g_rsum[BB * C5], g_rsq[BB * C5];
__device__ float g_pool[BB * 3000];
__device__ float g_z1[BB * 512], g_u1[BB * 512], g_z2[BB * 512];

// ----------------------------- helpers --------------------------------------
__device__ __forceinline__ uint32_t s2u(const void* p) {
    uint32_t a;
    asm("{ .reg .u64 t; cvta.to.shared.u64 t, %1; cvt.u32.u64 %0, t; }" : "=r"(a) : "l"(p));
    return a;
}
__device__ __forceinline__ void ldm_x4(uint32_t a[4], uint32_t addr) {
    asm volatile("ldmatrix.sync.aligned.m8n8.x4.shared.b16 {%0,%1,%2,%3}, [%4];"
                 : "=r"(a[0]), "=r"(a[1]), "=r"(a[2]), "=r"(a[3]) : "r"(addr));
}
__device__ __forceinline__ void mma16816(float c[4], const uint32_t a[4], const uint32_t b[2]) {
    asm volatile("mma.sync.aligned.m16n8k16.row.col.f32.f16.f16.f32 "
                 "{%0,%1,%2,%3}, {%4,%5,%6,%7}, {%8,%9}, {%0,%1,%2,%3};"
                 : "+f"(c[0]), "+f"(c[1]), "+f"(c[2]), "+f"(c[3])
                 : "r"(a[0]), "r"(a[1]), "r"(a[2]), "r"(a[3]), "r"(b[0]), "r"(b[1]));
}
__device__ __forceinline__ void cpa16(uint32_t dst, const void* src, int sz) {
    asm volatile("cp.async.ca.shared.global [%0], [%1], 16, %2;" :: "r"(dst), "l"(src), "r"(sz));
}
#define CP_COMMIT() asm volatile("cp.async.commit_group;" ::: "memory")
#define CP_WAIT1() asm volatile("cp.async.wait_group 1;" ::: "memory")
#define CP_WAIT0() asm volatile("cp.async.wait_group 0;" ::: "memory")

// ------------------------------ prep kernels --------------------------------
__global__ void xsplit(const float* __restrict__ x, __half* __restrict__ xh, __half* __restrict__ xl) {
    int idx = blockIdx.x * 256 + threadIdx.x;
    if (idx >= BB * T0 * 32) return;
    int f = idx & 31, bt = idx >> 5;
    float v = (f < F0) ? x[(size_t)bt * F0 + f] : 0.f;
    __half h = __float2half(v);
    xh[idx] = h;
    xl[idx] = __float2half(v - __half2float(h));
}

__global__ void fold_split(const float* __restrict__ w, const float* __restrict__ bias,
                           const float* __restrict__ mean, const float* __restrict__ istd,
                           const float* __restrict__ g, const float* __restrict__ be,
                           __half* __restrict__ wh, __half* __restrict__ wl, float* __restrict__ bp,
                           int Korig, int NOFF, int C, int Cpad, int Cout, int Kp) {
    int o = blockIdx.x;
    float part = 0.f;
    for (int k = threadIdx.x; k < Kp; k += 256) {
        int j = k / Cpad, c = k - j * Cpad;
        float wa = 0.f;
        if (o < Cout && c < C) {
            float a = 1.f, d = 0.f;
            if (mean) { a = istd[c] * (g ? g[c] : 1.f); d = (be ? be[c] : 0.f) - mean[c] * a; }
            float wv = w[(size_t)o * Korig + c * NOFF + j];
            wa = wv * a;
            part += wv * d;
        }
        __half h = __float2half(wa);
        wh[(size_t)o * Kp + k] = h;
        wl[(size_t)o * Kp + k] = __float2half(wa - __half2float(h));
    }
    __shared__ float sh[256];
    sh[threadIdx.x] = part;
    __syncthreads();
    for (int d2 = 128; d2 > 0; d2 >>= 1) {
        if (threadIdx.x < d2) sh[threadIdx.x] += sh[threadIdx.x + d2];
        __syncthreads();
    }
    if (threadIdx.x == 0) bp[o] = (o < Cout ? bias[o] : 0.f) + sh[0];
}

// -------------------------- mma.sync GEMM -----------------------------------
// CTA 128x128, BK=32, 8 warps (4m x 2n), warp 32x64, fp16 hi/lo 3-term.
// 2-stage cp.async pipeline (smem 2x40960 -> 2 CTAs/SM).
__global__ __launch_bounds__(256, 2)
void mma_gemm(const __half* __restrict__ Ah, const __half* __restrict__ Al,
              const __half* __restrict__ Wh, const __half* __restrict__ Wl,
              const float* __restrict__ bias,
              __half* __restrict__ Oh, __half* __restrict__ Ol,
              float* __restrict__ P5s, float* __restrict__ P5q,
              int Tin, int Tout, int Cpad, int step, int Kp, int Coutp, int act) {
    extern __shared__ char smem[];
    uint32_t su = s2u(smem);
    int tid = threadIdx.x, lane = tid & 31, wid = tid >> 5;
    int b = blockIdx.z, t0 = blockIdx.x * 128, obase = blockIdx.y * 128;
    int wm = wid >> 1, wn = wid & 1;
    int nk = Kp >> 5;

    float acc[2][8][4];
#pragma unroll
    for (int i = 0; i < 2; i++)
#pragma unroll
        for (int j = 0; j < 8; j++)
#pragma unroll
            for (int q = 0; q < 4; q++) acc[i][j][q] = 0.f;

    auto load_stage = [&](int buf, int kc) {
        int kc0 = kc << 5;
        int j = kc0 / Cpad, c0 = kc0 - j * Cpad, off = j * step;
        uint32_t sb = su + buf * 40960;
        const __half* pa[2] = {Ah, Al};
        const __half* pw[2] = {Wh, Wl};
#pragma unroll
        for (int h = 0; h < 2; h++) {
#pragma unroll
            for (int i = 0; i < 2; i++) {
                int e = tid + i * 256, r = e >> 2, c = e & 3;
                cpa16(sb + h * 10240 + r * 80 + c * 16,
                      pa[h] + ((size_t)b * Tin + t0 + off + r) * Cpad + c0 + c * 8,
                      (t0 + r < Tout) ? 16 : 0);
            }
#pragma unroll
            for (int i = 0; i < 2; i++) {
                int e = tid + i * 256, r = e >> 2, c = e & 3;
                cpa16(sb + 20480 + h * 10240 + r * 80 + c * 16,
                      pw[h] + ((size_t)(obase + r)) * Kp + kc0 + c * 8, 16);
            }
        }
        CP_COMMIT();
    };

    auto compute = [&](int buf) {
        uint32_t sb = su + buf * 40960;
#pragma unroll
        for (int ks = 0; ks < 2; ks++) {
            uint32_t ah[2][4], al[2][4];
#pragma unroll
            for (int mf = 0; mf < 2; mf++) {
                int row = wm * 32 + mf * 16 + (lane & 15);
                uint32_t addr = sb + row * 80 + (ks * 16 + ((lane >> 4) << 3)) * 2;
                ldm_x4(ah[mf], addr);
                ldm_x4(al[mf], addr + 10240);
            }
#pragma unroll
            for (int nb = 0; nb < 2; nb++) {
                uint32_t bh[4][2], bl[4][2];
#pragma unroll
                for (int qq = 0; qq < 2; qq++) {
                    int g = lane >> 3;
                    int rowb = wn * 64 + nb * 32 + qq * 16 + ((g >> 1) << 3) + (lane & 7);
                    uint32_t addr = sb + 20480 + rowb * 80 + (ks * 16 + ((g & 1) << 3)) * 2;
                    uint32_t th[4], tl[4];
                    ldm_x4(th, addr);
                    ldm_x4(tl, addr + 10240);
                    bh[qq * 2][0] = th[0]; bh[qq * 2][1] = th[1];
                    bh[qq * 2 + 1][0] = th[2]; bh[qq * 2 + 1][1] = th[3];
                    bl[qq * 2][0] = tl[0]; bl[qq * 2][1] = tl[1];
                    bl[qq * 2 + 1][0] = tl[2]; bl[qq * 2 + 1][1] = tl[3];
                }
#pragma unroll
                for (int mf = 0; mf < 2; mf++)
#pragma unroll
                    for (int q = 0; q < 4; q++) {
                        int nf = nb * 4 + q;
                        mma16816(acc[mf][nf], ah[mf], bh[q]);
                        mma16816(acc[mf][nf], ah[mf], bl[q]);
                        mma16816(acc[mf][nf], al[mf], bh[q]);
                    }
            }
        }
    };

    load_stage(0, 0);
    load_stage(1, 1);
    for (int kc = 0; kc < nk; kc++) {
        if (kc < nk - 2) CP_WAIT1(); else CP_WAIT0();
        __syncthreads();
        compute(kc & 1);
        __syncthreads();
        if (kc + 2 < nk) load_stage(kc & 1, kc + 2);
    }

    int l4 = lane >> 2, l2 = (lane & 3) << 1;
    if (!P5s) {
#pragma unroll
        for (int mf = 0; mf < 2; mf++)
#pragma unroll
            for (int hh = 0; hh < 2; hh++) {
                int t = t0 + wm * 32 + mf * 16 + l4 + hh * 8;
                if (t >= Tout) continue;
                size_t ro = ((size_t)b * Tout + t) * Coutp + obase + wn * 64;
#pragma unroll
                for (int nf = 0; nf < 8; nf++) {
                    int o = nf * 8 + l2;
                    float v0 = acc[mf][nf][hh * 2 + 0] + bias[obase + wn * 64 + o];
                    float v1 = acc[mf][nf][hh * 2 + 1] + bias[obase + wn * 64 + o + 1];
                    v0 = fmaxf(v0, 0.f); v1 = fmaxf(v1, 0.f);
                    if (act) { v0 = fminf(v0, 6.f); v1 = fminf(v1, 6.f); }
                    __half h0 = __float2half(v0), h1 = __float2half(v1);
                    *(__half2*)(Oh + ro + o) = __halves2half2(h0, h1);
                    *(__half2*)(Ol + ro + o) = __halves2half2(
                        __float2half(v0 - __half2float(h0)), __float2half(v1 - __half2float(h1)));
                }
            }
    } else {
        // stats mode: column (sum, sumsq) over this CTA's valid t rows
        float s_[8][2] = {}, q_[8][2] = {};
#pragma unroll
        for (int mf = 0; mf < 2; mf++)
#pragma unroll
            for (int hh = 0; hh < 2; hh++) {
                int t = t0 + wm * 32 + mf * 16 + l4 + hh * 8;
                bool tv = t < Tout;
#pragma unroll
                for (int nf = 0; nf < 8; nf++)
#pragma unroll
                    for (int e = 0; e < 2; e++) {
                        float v = acc[mf][nf][hh * 2 + e] + bias[obase + wn * 64 + nf * 8 + l2 + e];
                        v = fminf(fmaxf(v, 0.f), 6.f);
                        if (tv) { s_[nf][e] += v; q_[nf][e] += v * v; }
                    }
            }
#pragma unroll
        for (int nf = 0; nf < 8; nf++)
#pragma unroll
            for (int e = 0; e < 2; e++)
#pragma unroll
                for (int o = 4; o <= 16; o <<= 1) {
                    s_[nf][e] += __shfl_xor_sync(0xffffffffu, s_[nf][e], o);
                    q_[nf][e] += __shfl_xor_sync(0xffffffffu, q_[nf][e], o);
                }
        float* ss = (float*)smem;
        float* sq = ss + 128;
        __syncthreads();
        if (tid < 256) ss[tid] = 0.f;
        __syncthreads();
        if ((lane >> 2) == 0) {
#pragma unroll
            for (int nf = 0; nf < 8; nf++)
#pragma unroll
                for (int e = 0; e < 2; e++) {
                    int col = wn * 64 + nf * 8 + (lane & 3) * 2 + e;
                    atomicAdd(&ss[col], s_[nf][e]);
                    atomicAdd(&sq[col], q_[nf][e]);
                }
        }
        __syncthreads();
        if (tid < 128) {
            size_t pidx = ((size_t)blockIdx.x * BB + b) * Coutp + obase + tid;
            P5s[pidx] = ss[tid];
            P5q[pidx] = sq[tid];
        }
    }
}

// --------------------------- stats / tail -----------------------------------
__global__ void statpart(const __half* __restrict__ hi, const __half* __restrict__ lo,
                         float* __restrict__ ps, float* __restrict__ pq, int Mrows, int Cpad) {
    int c2 = blockIdx.x * 256 + threadIdx.x;
    int s = blockIdx.y, ns = gridDim.y;
    int per = (Mrows + ns - 1) / ns;
    int m0 = s * per, m1 = min(m0 + per, Mrows);
    const __half2* H = (const __half2*)hi;
    const __half2* L = (const __half2*)lo;
    int C2 = Cpad >> 1;
    float sx = 0.f, sy = 0.f, qx = 0.f, qy = 0.f;
    for (int m = m0; m < m1; m++) {
        float2 h = __half22float2(H[(size_t)m * C2 + c2]);
        float2 l = __half22float2(L[(size_t)m * C2 + c2]);
        float v0 = h.x + l.x, v1 = h.y + l.y;
        sx += v0; sy += v1; qx += v0 * v0; qy += v1 * v1;
    }
    ps[(size_t)s * Cpad + 2 * c2] = sx;
    ps[(size_t)s * Cpad + 2 * c2 + 1] = sy;
    pq[(size_t)s * Cpad + 2 * c2] = qx;
    pq[(size_t)s * Cpad + 2 * c2 + 1] = qy;
}
__global__ void statfin(const float* __restrict__ ps, const float* __restrict__ pq,
                        float* __restrict__ mean, float* __restrict__ istd, int Cpad, float N) {
    int c = blockIdx.x * 256 + threadIdx.x;
    if (c >= Cpad) return;
    float s = 0.f, q = 0.f;
    for (int i = 0; i < NS; i++) { s += ps[(size_t)i * Cpad + c]; q += pq[(size_t)i * Cpad + c]; }
    float m = s / N;
    mean[c] = m;
    istd[c] = rsqrtf(q / N - m * m + EPSF);
}
__global__ void part5reduce(const float* __restrict__ ps, const float* __restrict__ pq,
                            float* __restrict__ rsum, float* __restrict__ rsq) {
    int c = blockIdx.x * 256 + threadIdx.x;
    int b = blockIdx.y;
    if (c >= C5) return;
    float s = 0.f, q = 0.f;
    for (int i = 0; i < 16; i++) {
        s += ps[((size_t)i * BB + b) * C5P + c];
        q += pq[((size_t)i * BB + b) * C5P + c];
    }
    rsum[b * C5 + c] = s;
    rsq[b * C5 + c] = q;
}
__global__ void chstats5(const float* __restrict__ rsum, const float* __restrict__ rsq,
                         float* __restrict__ mean, float* __restrict__ istd) {
    int c = blockIdx.x * 256 + threadIdx.x;
    if (c >= C5) return;
    float s = 0.f, ss = 0.f;
    for (int b = 0; b < BB; b++) { s += rsum[b * C5 + c]; ss += rsq[b * C5 + c]; }
    float N = (float)BB * (float)T5;
    float m = s / N;
    mean[c] = m;
    istd[c] = rsqrtf(ss / N - m * m + EPSF);
}
__global__ void pool_kernel(const float* __restrict__ rsum, const float* __restrict__ rsq,
                            const float* __restrict__ m5, const float* __restrict__ i5,
                            const float* __restrict__ g5, const float* __restrict__ be5,
                            float* __restrict__ pooled) {
    int idx = blockIdx.x * 256 + threadIdx.x;
    if (idx >= BB * C5) return;
    int c = idx % C5, b = idx / C5;
    float Tf = (float)T5;
    float mt = rsum[b * C5 + c] / Tf;
    float vart = (rsq[b * C5 + c] - Tf * mt * mt) / (Tf - 1.f);
    float a = i5[c] * g5[c];
    float d = be5[c] - m5[c] * a;
    pooled[(size_t)b * 3000 + c] = a * mt + d;
    pooled[(size_t)b * 3000 + 1500 + c] = fabsf(a) * sqrtf(fmaxf(vart, 0.f));
}
__global__ void fc_kernel(const float* __restrict__ in, const float* __restrict__ w,
                          const float* __restrict__ bias, float* __restrict__ out, int K, int Cout) {
    int o = blockIdx.x, b = blockIdx.y;
    const float* ir = in + (size_t)b * K;
    const float* wr = w + (size_t)o * K;
    float s = 0.f;
    for (int k = threadIdx.x; k < K; k += 128) s += ir[k] * wr[k];
    __shared__ float sh[128];
    sh[threadIdx.x] = s;
    __syncthreads();
    for (int d = 64; d > 0; d >>= 1) {
        if (threadIdx.x < d) sh[threadIdx.x] += sh[threadIdx.x + d];
        __syncthreads();
    }
    if (threadIdx.x == 0) out[(size_t)b * Cout + o] = fminf(fmaxf(sh[0] + bias[o], 0.f), 6.f);
}
__global__ void bnc_kernel(const float* __restrict__ z, const float* __restrict__ g,
                           const float* __restrict__ be, float* __restrict__ out, int C) {
    int c = threadIdx.x + blockIdx.x * 256;
    if (c >= C) return;
    float s = 0.f, ss = 0.f;
    for (int b = 0; b < BB; b++) { float v = z[(size_t)b * C + c]; s += v; ss += v * v; }
    float m = s / (float)BB;
    float is = rsqrtf(ss / (float)BB - m * m + EPSF);
    for (int b = 0; b < BB; b++)
        out[(size_t)b * C + c] = (z[(size_t)b * C + c] - m) * is * g[c] + be[c];
}

// ------------------------------- host ---------------------------------------
static void* sa(const void* sym) { void* p = nullptr; cudaGetSymbolAddress(&p, sym); return p; }

extern "C" void kernel_launch(void* const* d_in, const int* in_sizes, int n_in,
                              void* d_out, int out_size) {
    const float* x = (const float*)d_in[0];
    const float *h1w = (const float*)d_in[1], *h1b = (const float*)d_in[2];
    const float *h2w = (const float*)d_in[3], *h2b = (const float*)d_in[4];
    const float *bn2g = (const float*)d_in[5], *bn2b = (const float*)d_in[6];
    const float *h3w = (const float*)d_in[7], *h3b = (const float*)d_in[8];
    const float *bn3g = (const float*)d_in[9], *bn3b = (const float*)d_in[10];
    const float *h4w = (const float*)d_in[11], *h4b = (const float*)d_in[12];
    const float *bn4g = (const float*)d_in[13], *bn4b = (const float*)d_in[14];
    const float *h5w = (const float*)d_in[15], *h5b = (const float*)d_in[16];
    const float *bn5g = (const float*)d_in[17], *bn5b = (const float*)d_in[18];
    const float *l1w = (const float*)d_in[19], *l1b = (const float*)d_in[20];
    const float *bn6g = (const float*)d_in[21], *bn6b = (const float*)d_in[22];
    const float *l2w = (const float*)d_in[23], *l2b = (const float*)d_in[24];
    const float *bn7g = (const float*)d_in[25], *bn7b = (const float*)d_in[26];

    __half *xh = (__half*)sa(g_xhi), *xl = (__half*)sa(g_xlo);
    __half *a1h = (__half*)sa(g_a1hi), *a1l = (__half*)sa(g_a1lo);
    __half *a2h = (__half*)sa(g_a2hi), *a2l = (__half*)sa(g_a2lo);
    __half *a3h = (__half*)sa(g_a3hi), *a3l = (__half*)sa(g_a3lo);
    __half *a4h = (__half*)sa(g_a4hi), *a4l = (__half*)sa(g_a4lo);
    __half *w1h = (__half*)sa(g_w1hi), *w1l = (__half*)sa(g_w1lo);
    __half *w2h = (__half*)sa(g_w2hi), *w2l = (__half*)sa(g_w2lo);
    __half *w3h = (__half*)sa(g_w3hi), *w3l = (__half*)sa(g_w3lo);
    __half *w4h = (__half*)sa(g_w4hi), *w4l = (__half*)sa(g_w4lo);
    __half *w5h = (__half*)sa(g_w5hi), *w5l = (__half*)sa(g_w5lo);
    float *b1 = (float*)sa(g_b1p), *b2 = (float*)sa(g_b2p), *b3 = (float*)sa(g_b3p);
    float *b4 = (float*)sa(g_b4p), *b5 = (float*)sa(g_b5p);
    float *ps = (float*)sa(g_ps), *pq = (float*)sa(g_pq);
    float *p5s = (float*)sa(g_p5s), *p5q = (float*)sa(g_p5q);
    float *m1 = (float*)sa(g_m1), *i1 = (float*)sa(g_i1), *m2 = (float*)sa(g_m2), *i2 = (float*)sa(g_i2);
    float *m3 = (float*)sa(g_m3), *i3 = (float*)sa(g_i3), *m4 = (float*)sa(g_m4), *i4 = (float*)sa(g_i4);
    float *m5 = (float*)sa(g_m5), *i5 = (float*)sa(g_i5);
    float *rsum = (float*)sa(g_rsum), *rsq = (float*)sa(g_rsq), *pool = (float*)sa(g_pool);
    float *z1 = (float*)sa(g_z1), *u1 = (float*)sa(g_u1), *z2 = (float*)sa(g_z2);

    const int SMEMB = 2 * 40960;
    cudaFuncSetAttribute(mma_gemm, cudaFuncAttributeMaxDynamicSharedMemorySize, SMEMB);

    xsplit<<<(BB * T0 * 32 + 255) / 256, 256>>>(x, xh, xl);

    // L1: K'=160 (5 offset blocks, Cpad=32), step 1, relu
    fold_split<<<512, 256>>>(h1w, h1b, nullptr, nullptr, nullptr, nullptr, w1h, w1l, b1, 100, 5, 20, 32, 512, 160);
    mma_gemm<<<dim3(16, 4, BB), 256, SMEMB>>>(xh, xl, w1h, w1l, b1, a1h, a1l, nullptr, nullptr, T0, T1, 32, 1, 160, 512, 0);
    statpart<<<dim3(1, NS), 256>>>(a1h, a1l, ps, pq, BB * T1, 512);
    statfin<<<2, 256>>>(ps, pq, m1, i1, 512, (float)BB * (float)T1);

    // L2: fold bn1, offsets {0,2,4}, relu
    fold_split<<<512, 256>>>(h2w, h2b, m1, i1, nullptr, nullptr, w2h, w2l, b2, 1536, 3, 512, 512, 512, 1536);
    mma_gemm<<<dim3(16, 4, BB), 256, SMEMB>>>(a1h, a1l, w2h, w2l, b2, a2h, a2l, nullptr, nullptr, T1, T2, 512, 2, 1536, 512, 0);
    statpart<<<dim3(1, NS), 256>>>(a2h, a2l, ps, pq, BB * T2, 512);
    statfin<<<2, 256>>>(ps, pq, m2, i2, 512, (float)BB * (float)T2);

    // L3: fold bn2, offsets {0,3,6}, relu
    fold_split<<<512, 256>>>(h3w, h3b, m2, i2, bn2g, bn2b, w3h, w3l, b3, 1536, 3, 512, 512, 512, 1536);
    mma_gemm<<<dim3(16, 4, BB), 256, SMEMB>>>(a2h, a2l, w3h, w3l, b3, a3h, a3l, nullptr, nullptr, T2, T3, 512, 3, 1536, 512, 0);
    statpart<<<dim3(1, NS), 256>>>(a3h, a3l, ps, pq, BB * T3, 512);
    statfin<<<2, 256>>>(ps, pq, m3, i3, 512, (float)BB * (float)T3);

    // L4: fold bn3, 512->512, relu6
    fold_split<<<512, 256>>>(h4w, h4b, m3, i3, bn3g, bn3b, w4h, w4l, b4, 512, 1, 512, 512, 512, 512);
    mma_gemm<<<dim3(16, 4, BB), 256, SMEMB>>>(a3h, a3l, w4h, w4l, b4, a4h, a4l, nullptr, nullptr, T3, T3, 512, 0, 512, 512, 1);
    statpart<<<dim3(1, NS), 256>>>(a4h, a4l, ps, pq, BB * T3, 512);
    statfin<<<2, 256>>>(ps, pq, m4, i4, 512, (float)BB * (float)T3);

    // L5: fold bn4, 512->1500 (pad 1536), relu6; stats fused into epilogue
    fold_split<<<C5P, 256>>>(h5w, h5b, m4, i4, bn4g, bn4b, w5h, w5l, b5, 512, 1, 512, 512, C5, 512);
    mma_gemm<<<dim3(16, 12, BB), 256, SMEMB>>>(a4h, a4l, w5h, w5l, b5, nullptr, nullptr, p5s, p5q, T3, T5, 512, 0, 512, C5P, 1);

    // stats pooling (bn5 folded analytically)
    part5reduce<<<dim3(6, BB), 256>>>(p5s, p5q, rsum, rsq);
    chstats5<<<6, 256>>>(rsum, rsq, m5, i5);
    pool_kernel<<<(BB * C5 + 255) / 256, 256>>>(rsum, rsq, m5, i5, bn5g, bn5b, pool);

    // tail FCs
    fc_kernel<<<dim3(512, BB), 128>>>(pool, l1w, l1b, z1, 3000, 512);
    bnc_kernel<<<2, 256>>>(z1, bn6g, bn6b, u1, 512);
    fc_kernel<<<dim3(512, BB), 128>>>(u1, l2w, l2b, z2, 512, 512);
    bnc_kernel<<<2, 256>>>(z2, bn7g, bn7b, (float*)d_out, 512);
}

// round 8
// speedup vs baseline: 1.8161x; 1.0013x over previous
#include <cuda_runtime.h>
#include <cuda_fp16.h>
#include <cstdint>
#include <cstddef>

#define EPSF 1e-5f
constexpr int BB = 32, F0 = 20, T0 = 2048;
constexpr int T1 = 2044, T2 = 2040, T3 = 2034, T5 = 2034;
constexpr int C5 = 1500, C5P = 1536;
constexpr int NSL = 512;   // stat partial slices for L1-4 (16 bx * 32 b)

// ------------------------------- scratch -----------------------------------
__device__ __align__(16) __half g_xhi[(size_t)BB * T0 * 32],  g_xlo[(size_t)BB * T0 * 32];
__device__ __align__(16) __half g_a1hi[(size_t)BB * T1 * 512], g_a1lo[(size_t)BB * T1 * 512];
__device__ __align__(16) __half g_a2hi[(size_t)BB * T2 * 512], g_a2lo[(size_t)BB * T2 * 512];
__device__ __align__(16) __half g_a3hi[(size_t)BB * T3 * 512], g_a3lo[(size_t)BB * T3 * 512];
__device__ __align__(16) __half g_a4hi[(size_t)BB * T3 * 512], g_a4lo[(size_t)BB * T3 * 512];
__device__ __align__(16) __half g_w1hi[512 * 160],  g_w1lo[512 * 160];
__device__ __align__(16) __half g_w2hi[512 * 1536], g_w2lo[512 * 1536];
__device__ __align__(16) __half g_w3hi[512 * 1536], g_w3lo[512 * 1536];
__device__ __align__(16) __half g_w4hi[512 * 512],  g_w4lo[512 * 512];
__device__ __align__(16) __half g_w5hi[C5P * 512],  g_w5lo[C5P * 512];
__device__ float g_b1p[512], g_b2p[512], g_b3p[512], g_b4p[512], g_b5p[C5P];
__device__ float g_ps[NSL * 512], g_pq[NSL * 512];
__device__ float g_p5s[16 * BB * C5P], g_p5q[16 * BB * C5P];
__device__ float g_m1[512], g_i1[512], g_m2[512], g_i2[512];
__device__ float g_m3[512], g_i3[512], g_m4[512], g_i4[512];
__device__ float g_m5[C5], g_i5[C5];
__device__ float g_rsum[BB * C5], g_rsq[BB * C5];
__device__ float g_pool[BB * 3000];
__device__ float g_z1[BB * 512], g_u1[BB * 512], g_z2[BB * 512];

// ----------------------------- helpers --------------------------------------
__device__ __forceinline__ uint32_t s2u(const void* p) {
    uint32_t a;
    asm("{ .reg .u64 t; cvta.to.shared.u64 t, %1; cvt.u32.u64 %0, t; }" : "=r"(a) : "l"(p));
    return a;
}
__device__ __forceinline__ void ldm_x4(uint32_t a[4], uint32_t addr) {
    asm volatile("ldmatrix.sync.aligned.m8n8.x4.shared.b16 {%0,%1,%2,%3}, [%4];"
                 : "=r"(a[0]), "=r"(a[1]), "=r"(a[2]), "=r"(a[3]) : "r"(addr));
}
__device__ __forceinline__ void mma16816(float c[4], const uint32_t a[4], const uint32_t b[2]) {
    asm volatile("mma.sync.aligned.m16n8k16.row.col.f32.f16.f16.f32 "
                 "{%0,%1,%2,%3}, {%4,%5,%6,%7}, {%8,%9}, {%0,%1,%2,%3};"
                 : "+f"(c[0]), "+f"(c[1]), "+f"(c[2]), "+f"(c[3])
                 : "r"(a[0]), "r"(a[1]), "r"(a[2]), "r"(a[3]), "r"(b[0]), "r"(b[1]));
}
__device__ __forceinline__ void cpa16(uint32_t dst, const void* src, int sz) {
    asm volatile("cp.async.ca.shared.global [%0], [%1], 16, %2;" :: "r"(dst), "l"(src), "r"(sz));
}
#define CP_COMMIT() asm volatile("cp.async.commit_group;" ::: "memory")
#define CP_WAIT1() asm volatile("cp.async.wait_group 1;" ::: "memory")
#define CP_WAIT0() asm volatile("cp.async.wait_group 0;" ::: "memory")

// ------------------------------ prep kernels --------------------------------
__global__ void xsplit(const float* __restrict__ x, __half* __restrict__ xh, __half* __restrict__ xl) {
    int idx = blockIdx.x * 256 + threadIdx.x;
    if (idx >= BB * T0 * 32) return;
    int f = idx & 31, bt = idx >> 5;
    float v = (f < F0) ? x[(size_t)bt * F0 + f] : 0.f;
    __half h = __float2half(v);
    xh[idx] = h;
    xl[idx] = __float2half(v - __half2float(h));
}

__global__ void fold_split(const float* __restrict__ w, const float* __restrict__ bias,
                           const float* __restrict__ mean, const float* __restrict__ istd,
                           const float* __restrict__ g, const float* __restrict__ be,
                           __half* __restrict__ wh, __half* __restrict__ wl, float* __restrict__ bp,
                           int Korig, int NOFF, int C, int Cpad, int Cout, int Kp) {
    int o = blockIdx.x;
    float part = 0.f;
    for (int k = threadIdx.x; k < Kp; k += 256) {
        int j = k / Cpad, c = k - j * Cpad;
        float wa = 0.f;
        if (o < Cout && c < C) {
            float a = 1.f, d = 0.f;
            if (mean) { a = istd[c] * (g ? g[c] : 1.f); d = (be ? be[c] : 0.f) - mean[c] * a; }
            float wv = w[(size_t)o * Korig + c * NOFF + j];
            wa = wv * a;
            part += wv * d;
        }
        __half h = __float2half(wa);
        wh[(size_t)o * Kp + k] = h;
        wl[(size_t)o * Kp + k] = __float2half(wa - __half2float(h));
    }
    __shared__ float sh[256];
    sh[threadIdx.x] = part;
    __syncthreads();
    for (int d2 = 128; d2 > 0; d2 >>= 1) {
        if (threadIdx.x < d2) sh[threadIdx.x] += sh[threadIdx.x + d2];
        __syncthreads();
    }
    if (threadIdx.x == 0) bp[o] = (o < Cout ? bias[o] : 0.f) + sh[0];
}

// -------------------------- mma.sync GEMM -----------------------------------
// CTA 128x128, BK=32, 8 warps (4m x 2n), warp 32x64, fp16 hi/lo 3-term.
// 2-stage cp.async pipeline (2x40960B smem -> 2 CTAs/SM).
// Epilogue: writes activations (if Oh) and/or per-CTA column (sum,sumsq)
// partials at [bx*BB+b][col] (if Ps) — fused BN/pooling statistics.
__global__ __launch_bounds__(256, 2)
void mma_gemm(const __half* __restrict__ Ah, const __half* __restrict__ Al,
              const __half* __restrict__ Wh, const __half* __restrict__ Wl,
              const float* __restrict__ bias,
              __half* __restrict__ Oh, __half* __restrict__ Ol,
              float* __restrict__ Ps, float* __restrict__ Pq,
              int Tin, int Tout, int Cpad, int step, int Kp, int Coutp, int act) {
    extern __shared__ char smem[];
    uint32_t su = s2u(smem);
    int tid = threadIdx.x, lane = tid & 31, wid = tid >> 5;
    int b = blockIdx.z, t0 = blockIdx.x * 128, obase = blockIdx.y * 128;
    int wm = wid >> 1, wn = wid & 1;
    int nk = Kp >> 5;

    float acc[2][8][4];
#pragma unroll
    for (int i = 0; i < 2; i++)
#pragma unroll
        for (int j = 0; j < 8; j++)
#pragma unroll
            for (int q = 0; q < 4; q++) acc[i][j][q] = 0.f;

    auto load_stage = [&](int buf, int kc) {
        int kc0 = kc << 5;
        int j = kc0 / Cpad, c0 = kc0 - j * Cpad, off = j * step;
        uint32_t sb = su + buf * 40960;
        const __half* pa[2] = {Ah, Al};
        const __half* pw[2] = {Wh, Wl};
#pragma unroll
        for (int h = 0; h < 2; h++) {
#pragma unroll
            for (int i = 0; i < 2; i++) {
                int e = tid + i * 256, r = e >> 2, c = e & 3;
                cpa16(sb + h * 10240 + r * 80 + c * 16,
                      pa[h] + ((size_t)b * Tin + t0 + off + r) * Cpad + c0 + c * 8,
                      (t0 + r < Tout) ? 16 : 0);
            }
#pragma unroll
            for (int i = 0; i < 2; i++) {
                int e = tid + i * 256, r = e >> 2, c = e & 3;
                cpa16(sb + 20480 + h * 10240 + r * 80 + c * 16,
                      pw[h] + ((size_t)(obase + r)) * Kp + kc0 + c * 8, 16);
            }
        }
        CP_COMMIT();
    };

    auto compute = [&](int buf) {
        uint32_t sb = su + buf * 40960;
#pragma unroll
        for (int ks = 0; ks < 2; ks++) {
            uint32_t ah[2][4], al[2][4];
#pragma unroll
            for (int mf = 0; mf < 2; mf++) {
                int row = wm * 32 + mf * 16 + (lane & 15);
                uint32_t addr = sb + row * 80 + (ks * 16 + ((lane >> 4) << 3)) * 2;
                ldm_x4(ah[mf], addr);
                ldm_x4(al[mf], addr + 10240);
            }
#pragma unroll
            for (int nb = 0; nb < 2; nb++) {
                uint32_t bh[4][2], bl[4][2];
#pragma unroll
                for (int qq = 0; qq < 2; qq++) {
                    int g = lane >> 3;
                    int rowb = wn * 64 + nb * 32 + qq * 16 + ((g >> 1) << 3) + (lane & 7);
                    uint32_t addr = sb + 20480 + rowb * 80 + (ks * 16 + ((g & 1) << 3)) * 2;
                    uint32_t th[4], tl[4];
                    ldm_x4(th, addr);
                    ldm_x4(tl, addr + 10240);
                    bh[qq * 2][0] = th[0]; bh[qq * 2][1] = th[1];
                    bh[qq * 2 + 1][0] = th[2]; bh[qq * 2 + 1][1] = th[3];
                    bl[qq * 2][0] = tl[0]; bl[qq * 2][1] = tl[1];
                    bl[qq * 2 + 1][0] = tl[2]; bl[qq * 2 + 1][1] = tl[3];
                }
#pragma unroll
                for (int mf = 0; mf < 2; mf++)
#pragma unroll
                    for (int q = 0; q < 4; q++) {
                        int nf = nb * 4 + q;
                        mma16816(acc[mf][nf], ah[mf], bh[q]);
                        mma16816(acc[mf][nf], ah[mf], bl[q]);
                        mma16816(acc[mf][nf], al[mf], bh[q]);
                    }
            }
        }
    };

    load_stage(0, 0);
    load_stage(1, 1);
    for (int kc = 0; kc < nk; kc++) {
        if (kc < nk - 2) CP_WAIT1(); else CP_WAIT0();
        __syncthreads();
        compute(kc & 1);
        __syncthreads();
        if (kc + 2 < nk) load_stage(kc & 1, kc + 2);
    }

    // ------- fused epilogue: activations + column stats -------
    int l4 = lane >> 2, l2 = (lane & 3) << 1;
    float s_[8][2] = {}, q_[8][2] = {};
#pragma unroll
    for (int mf = 0; mf < 2; mf++)
#pragma unroll
        for (int hh = 0; hh < 2; hh++) {
            int t = t0 + wm * 32 + mf * 16 + l4 + hh * 8;
            bool tv = t < Tout;
            size_t ro = ((size_t)b * Tout + t) * Coutp + obase + wn * 64;
#pragma unroll
            for (int nf = 0; nf < 8; nf++) {
                int o = nf * 8 + l2;
                float v0 = acc[mf][nf][hh * 2 + 0] + bias[obase + wn * 64 + o];
                float v1 = acc[mf][nf][hh * 2 + 1] + bias[obase + wn * 64 + o + 1];
                v0 = fmaxf(v0, 0.f); v1 = fmaxf(v1, 0.f);
                if (act) { v0 = fminf(v0, 6.f); v1 = fminf(v1, 6.f); }
                if (tv) {
                    s_[nf][0] += v0; q_[nf][0] += v0 * v0;
                    s_[nf][1] += v1; q_[nf][1] += v1 * v1;
                    if (Oh) {
                        __half h0 = __float2half(v0), h1 = __float2half(v1);
                        *(__half2*)(Oh + ro + o) = __halves2half2(h0, h1);
                        *(__half2*)(Ol + ro + o) = __halves2half2(
                            __float2half(v0 - __half2float(h0)), __float2half(v1 - __half2float(h1)));
                    }
                }
            }
        }
    if (Ps) {
#pragma unroll
        for (int nf = 0; nf < 8; nf++)
#pragma unroll
            for (int e = 0; e < 2; e++)
#pragma unroll
                for (int o = 4; o <= 16; o <<= 1) {
                    s_[nf][e] += __shfl_xor_sync(0xffffffffu, s_[nf][e], o);
                    q_[nf][e] += __shfl_xor_sync(0xffffffffu, q_[nf][e], o);
                }
        float* ss = (float*)smem;
        float* sq = ss + 128;
        __syncthreads();
        if (tid < 256) ss[tid] = 0.f;
        __syncthreads();
        if ((lane >> 2) == 0) {
#pragma unroll
            for (int nf = 0; nf < 8; nf++)
#pragma unroll
                for (int e = 0; e < 2; e++) {
                    int col = wn * 64 + nf * 8 + (lane & 3) * 2 + e;
                    atomicAdd(&ss[col], s_[nf][e]);
                    atomicAdd(&sq[col], q_[nf][e]);
                }
        }
        __syncthreads();
        if (tid < 128) {
            size_t pidx = ((size_t)blockIdx.x * BB + b) * Coutp + obase + tid;
            Ps[pidx] = ss[tid];
            Pq[pidx] = sq[tid];
        }
    }
}

// --------------------------- stats / tail -----------------------------------
__global__ void statfin(const float* __restrict__ ps, const float* __restrict__ pq,
                        float* __restrict__ mean, float* __restrict__ istd,
                        int Cpad, int np, float N) {
    int c = blockIdx.x * 256 + threadIdx.x;
    if (c >= Cpad) return;
    float s = 0.f, q = 0.f;
    for (int i = 0; i < np; i++) { s += ps[(size_t)i * Cpad + c]; q += pq[(size_t)i * Cpad + c]; }
    float m = s / N;
    mean[c] = m;
    istd[c] = rsqrtf(q / N - m * m + EPSF);
}
__global__ void part5reduce(const float* __restrict__ ps, const float* __restrict__ pq,
                            float* __restrict__ rsum, float* __restrict__ rsq) {
    int c = blockIdx.x * 256 + threadIdx.x;
    int b = blockIdx.y;
    if (c >= C5) return;
    float s = 0.f, q = 0.f;
    for (int i = 0; i < 16; i++) {
        s += ps[((size_t)i * BB + b) * C5P + c];
        q += pq[((size_t)i * BB + b) * C5P + c];
    }
    rsum[b * C5 + c] = s;
    rsq[b * C5 + c] = q;
}
__global__ void chstats5(const float* __restrict__ rsum, const float* __restrict__ rsq,
                         float* __restrict__ mean, float* __restrict__ istd) {
    int c = blockIdx.x * 256 + threadIdx.x;
    if (c >= C5) return;
    float s = 0.f, ss = 0.f;
    for (int b = 0; b < BB; b++) { s += rsum[b * C5 + c]; ss += rsq[b * C5 + c]; }
    float N = (float)BB * (float)T5;
    float m = s / N;
    mean[c] = m;
    istd[c] = rsqrtf(ss / N - m * m + EPSF);
}
__global__ void pool_kernel(const float* __restrict__ rsum, const float* __restrict__ rsq,
                            const float* __restrict__ m5, const float* __restrict__ i5,
                            const float* __restrict__ g5, const float* __restrict__ be5,
                            float* __restrict__ pooled) {
    int idx = blockIdx.x * 256 + threadIdx.x;
    if (idx >= BB * C5) return;
    int c = idx % C5, b = idx / C5;
    float Tf = (float)T5;
    float mt = rsum[b * C5 + c] / Tf;
    float vart = (rsq[b * C5 + c] - Tf * mt * mt) / (Tf - 1.f);
    float a = i5[c] * g5[c];
    float d = be5[c] - m5[c] * a;
    pooled[(size_t)b * 3000 + c] = a * mt + d;
    pooled[(size_t)b * 3000 + 1500 + c] = fabsf(a) * sqrtf(fmaxf(vart, 0.f));
}
__global__ void fc_kernel(const float* __restrict__ in, const float* __restrict__ w,
                          const float* __restrict__ bias, float* __restrict__ out, int K, int Cout) {
    int o = blockIdx.x, b = blockIdx.y;
    const float* ir = in + (size_t)b * K;
    const float* wr = w + (size_t)o * K;
    float s = 0.f;
    for (int k = threadIdx.x; k < K; k += 128) s += ir[k] * wr[k];
    __shared__ float sh[128];
    sh[threadIdx.x] = s;
    __syncthreads();
    for (int d = 64; d > 0; d >>= 1) {
        if (threadIdx.x < d) sh[threadIdx.x] += sh[threadIdx.x + d];
        __syncthreads();
    }
    if (threadIdx.x == 0) out[(size_t)b * Cout + o] = fminf(fmaxf(sh[0] + bias[o], 0.f), 6.f);
}
__global__ void bnc_kernel(const float* __restrict__ z, const float* __restrict__ g,
                           const float* __restrict__ be, float* __restrict__ out, int C) {
    int c = threadIdx.x + blockIdx.x * 256;
    if (c >= C) return;
    float s = 0.f, ss = 0.f;
    for (int b = 0; b < BB; b++) { float v = z[(size_t)b * C + c]; s += v; ss += v * v; }
    float m = s / (float)BB;
    float is = rsqrtf(ss / (float)BB - m * m + EPSF);
    for (int b = 0; b < BB; b++)
        out[(size_t)b * C + c] = (z[(size_t)b * C + c] - m) * is * g[c] + be[c];
}

// ------------------------------- host ---------------------------------------
static void* sa(const void* sym) { void* p = nullptr; cudaGetSymbolAddress(&p, sym); return p; }

extern "C" void kernel_launch(void* const* d_in, const int* in_sizes, int n_in,
                              void* d_out, int out_size) {
    const float* x = (const float*)d_in[0];
    const float *h1w = (const float*)d_in[1], *h1b = (const float*)d_in[2];
    const float *h2w = (const float*)d_in[3], *h2b = (const float*)d_in[4];
    const float *bn2g = (const float*)d_in[5], *bn2b = (const float*)d_in[6];
    const float *h3w = (const float*)d_in[7], *h3b = (const float*)d_in[8];
    const float *bn3g = (const float*)d_in[9], *bn3b = (const float*)d_in[10];
    const float *h4w = (const float*)d_in[11], *h4b = (const float*)d_in[12];
    const float *bn4g = (const float*)d_in[13], *bn4b = (const float*)d_in[14];
    const float *h5w = (const float*)d_in[15], *h5b = (const float*)d_in[16];
    const float *bn5g = (const float*)d_in[17], *bn5b = (const float*)d_in[18];
    const float *l1w = (const float*)d_in[19], *l1b = (const float*)d_in[20];
    const float *bn6g = (const float*)d_in[21], *bn6b = (const float*)d_in[22];
    const float *l2w = (const float*)d_in[23], *l2b = (const float*)d_in[24];
    const float *bn7g = (const float*)d_in[25], *bn7b = (const float*)d_in[26];

    __half *xh = (__half*)sa(g_xhi), *xl = (__half*)sa(g_xlo);
    __half *a1h = (__half*)sa(g_a1hi), *a1l = (__half*)sa(g_a1lo);
    __half *a2h = (__half*)sa(g_a2hi), *a2l = (__half*)sa(g_a2lo);
    __half *a3h = (__half*)sa(g_a3hi), *a3l = (__half*)sa(g_a3lo);
    __half *a4h = (__half*)sa(g_a4hi), *a4l = (__half*)sa(g_a4lo);
    __half *w1h = (__half*)sa(g_w1hi), *w1l = (__half*)sa(g_w1lo);
    __half *w2h = (__half*)sa(g_w2hi), *w2l = (__half*)sa(g_w2lo);
    __half *w3h = (__half*)sa(g_w3hi), *w3l = (__half*)sa(g_w3lo);
    __half *w4h = (__half*)sa(g_w4hi), *w4l = (__half*)sa(g_w4lo);
    __half *w5h = (__half*)sa(g_w5hi), *w5l = (__half*)sa(g_w5lo);
    float *b1 = (float*)sa(g_b1p), *b2 = (float*)sa(g_b2p), *b3 = (float*)sa(g_b3p);
    float *b4 = (float*)sa(g_b4p), *b5 = (float*)sa(g_b5p);
    float *ps = (float*)sa(g_ps), *pq = (float*)sa(g_pq);
    float *p5s = (float*)sa(g_p5s), *p5q = (float*)sa(g_p5q);
    float *m1 = (float*)sa(g_m1), *i1 = (float*)sa(g_i1), *m2 = (float*)sa(g_m2), *i2 = (float*)sa(g_i2);
    float *m3 = (float*)sa(g_m3), *i3 = (float*)sa(g_i3), *m4 = (float*)sa(g_m4), *i4 = (float*)sa(g_i4);
    float *m5 = (float*)sa(g_m5), *i5 = (float*)sa(g_i5);
    float *rsum = (float*)sa(g_rsum), *rsq = (float*)sa(g_rsq), *pool = (float*)sa(g_pool);
    float *z1 = (float*)sa(g_z1), *u1 = (float*)sa(g_u1), *z2 = (float*)sa(g_z2);

    const int SMEMB = 2 * 40960;
    cudaFuncSetAttribute(mma_gemm, cudaFuncAttributeMaxDynamicSharedMemorySize, SMEMB);

    xsplit<<<(BB * T0 * 32 + 255) / 256, 256>>>(x, xh, xl);

    // L1: K'=160 (5 offset blocks, Cpad=32), step 1, relu; stats fused
    fold_split<<<512, 256>>>(h1w, h1b, nullptr, nullptr, nullptr, nullptr, w1h, w1l, b1, 100, 5, 20, 32, 512, 160);
    mma_gemm<<<dim3(16, 4, BB), 256, SMEMB>>>(xh, xl, w1h, w1l, b1, a1h, a1l, ps, pq, T0, T1, 32, 1, 160, 512, 0);
    statfin<<<2, 256>>>(ps, pq, m1, i1, 512, NSL, (float)BB * (float)T1);

    // L2: fold bn1, offsets {0,2,4}, relu; stats fused
    fold_split<<<512, 256>>>(h2w, h2b, m1, i1, nullptr, nullptr, w2h, w2l, b2, 1536, 3, 512, 512, 512, 1536);
    mma_gemm<<<dim3(16, 4, BB), 256, SMEMB>>>(a1h, a1l, w2h, w2l, b2, a2h, a2l, ps, pq, T1, T2, 512, 2, 1536, 512, 0);
    statfin<<<2, 256>>>(ps, pq, m2, i2, 512, NSL, (float)BB * (float)T2);

    // L3: fold bn2, offsets {0,3,6}, relu; stats fused
    fold_split<<<512, 256>>>(h3w, h3b, m2, i2, bn2g, bn2b, w3h, w3l, b3, 1536, 3, 512, 512, 512, 1536);
    mma_gemm<<<dim3(16, 4, BB), 256, SMEMB>>>(a2h, a2l, w3h, w3l, b3, a3h, a3l, ps, pq, T2, T3, 512, 3, 1536, 512, 0);
    statfin<<<2, 256>>>(ps, pq, m3, i3, 512, NSL, (float)BB * (float)T3);

    // L4: fold bn3, 512->512, relu6; stats fused
    fold_split<<<512, 256>>>(h4w, h4b, m3, i3, bn3g, bn3b, w4h, w4l, b4, 512, 1, 512, 512, 512, 512);
    mma_gemm<<<dim3(16, 4, BB), 256, SMEMB>>>(a3h, a3l, w4h, w4l, b4, a4h, a4l, ps, pq, T3, T3, 512, 0, 512, 512, 1);
    statfin<<<2, 256>>>(ps, pq, m4, i4, 512, NSL, (float)BB * (float)T3);

    // L5: fold bn4, 512->1500 (pad 1536), relu6; stats-only epilogue
    fold_split<<<C5P, 256>>>(h5w, h5b, m4, i4, bn4g, bn4b, w5h, w5l, b5, 512, 1, 512, 512, C5, 512);
    mma_gemm<<<dim3(16, 12, BB), 256, SMEMB>>>(a4h, a4l, w5h, w5l, b5, nullptr, nullptr, p5s, p5q, T3, T5, 512, 0, 512, C5P, 1);

    // stats pooling (bn5 folded analytically)
    part5reduce<<<dim3(6, BB), 256>>>(p5s, p5q, rsum, rsq);
    chstats5<<<6, 256>>>(rsum, rsq, m5, i5);
    pool_kernel<<<(BB * C5 + 255) / 256, 256>>>(rsum, rsq, m5, i5, bn5g, bn5b, pool);

    // tail FCs
    fc_kernel<<<dim3(512, BB), 128>>>(pool, l1w, l1b, z1, 3000, 512);
    bnc_kernel<<<2, 256>>>(z1, bn6g, bn6b, u1, 512);
    fc_kernel<<<dim3(512, BB), 128>>>(u1, l2w, l2b, z2, 512, 512);
    bnc_kernel<<<2, 256>>>(z2, bn7g, bn7b, (float*)d_out, 512);
}

// round 11
// speedup vs baseline: 1.9354x; 1.0657x over previous
#include <cuda_runtime.h>
#include <cuda_fp16.h>
#include <cstdint>
#include <cstddef>

#define EPSF 1e-5f
constexpr int BB = 32, F0 = 20, T0 = 2048;
constexpr int T1 = 2044, T2 = 2040, T3 = 2034, T5 = 2034;
constexpr int C5 = 1500, C5P = 1536;
constexpr int NSL = 512;   // stat partial slices for L1-4 (16 bx * 32 b)

// ------------------------------- scratch -----------------------------------
__device__ __align__(16) __half g_xhi[(size_t)BB * T0 * 32],  g_xlo[(size_t)BB * T0 * 32];
__device__ __align__(16) __half g_a1hi[(size_t)BB * T1 * 512], g_a1lo[(size_t)BB * T1 * 512];
__device__ __align__(16) __half g_a2hi[(size_t)BB * T2 * 512], g_a2lo[(size_t)BB * T2 * 512];
__device__ __align__(16) __half g_a3hi[(size_t)BB * T3 * 512], g_a3lo[(size_t)BB * T3 * 512];
__device__ __align__(16) __half g_a4hi[(size_t)BB * T3 * 512], g_a4lo[(size_t)BB * T3 * 512];
__device__ __align__(16) __half g_w1hi[512 * 160],  g_w1lo[512 * 160];
__device__ __align__(16) __half g_w2hi[512 * 1536], g_w2lo[512 * 1536];
__device__ __align__(16) __half g_w3hi[512 * 1536], g_w3lo[512 * 1536];
__device__ __align__(16) __half g_w4hi[512 * 512],  g_w4lo[512 * 512];
__device__ __align__(16) __half g_w5hi[C5P * 512],  g_w5lo[C5P * 512];
__device__ float g_b1p[512], g_b2p[512], g_b3p[512], g_b4p[512], g_b5p[C5P];
__device__ float g_ps[NSL * 512], g_pq[NSL * 512];
__device__ float g_pm[16 * 512], g_qm[16 * 512];
__device__ float g_p5s[16 * BB * C5P], g_p5q[16 * BB * C5P];
__device__ float g_m1[512], g_i1[512], g_m2[512], g_i2[512];
__device__ float g_m3[512], g_i3[512], g_m4[512], g_i4[512];
__device__ float g_m5[C5], g_i5[C5];
__device__ float g_rsum[BB * C5], g_rsq[BB * C5];
__device__ float g_pool[BB * 3000];
__device__ float g_z1[BB * 512], g_u1[BB * 512], g_z2[BB * 512];

// ----------------------------- helpers --------------------------------------
__device__ __forceinline__ uint32_t s2u(const void* p) {
    uint32_t a;
    asm("{ .reg .u64 t; cvta.to.shared.u64 t, %1; cvt.u32.u64 %0, t; }" : "=r"(a) : "l"(p));
    return a;
}
__device__ __forceinline__ void ldm_x4(uint32_t a[4], uint32_t addr) {
    asm volatile("ldmatrix.sync.aligned.m8n8.x4.shared.b16 {%0,%1,%2,%3}, [%4];"
                 : "=r"(a[0]), "=r"(a[1]), "=r"(a[2]), "=r"(a[3]) : "r"(addr));
}
__device__ __forceinline__ void mma16816(float c[4], const uint32_t a[4], const uint32_t b[2]) {
    asm volatile("mma.sync.aligned.m16n8k16.row.col.f32.f16.f16.f32 "
                 "{%0,%1,%2,%3}, {%4,%5,%6,%7}, {%8,%9}, {%0,%1,%2,%3};"
                 : "+f"(c[0]), "+f"(c[1]), "+f"(c[2]), "+f"(c[3])
                 : "r"(a[0]), "r"(a[1]), "r"(a[2]), "r"(a[3]), "r"(b[0]), "r"(b[1]));
}
__device__ __forceinline__ void cpa16(uint32_t dst, const void* src, int sz) {
    asm volatile("cp.async.ca.shared.global [%0], [%1], 16, %2;" :: "r"(dst), "l"(src), "r"(sz));
}
#define CP_COMMIT() asm volatile("cp.async.commit_group;" ::: "memory")
#define CP_WAIT1() asm volatile("cp.async.wait_group 1;" ::: "memory")
#define CP_WAIT0() asm volatile("cp.async.wait_group 0;" ::: "memory")

// ------------------------------ prep kernels --------------------------------
__global__ void xsplit(const float* __restrict__ x, __half* __restrict__ xh, __half* __restrict__ xl) {
    int idx = blockIdx.x * 256 + threadIdx.x;
    if (idx >= BB * T0 * 32) return;
    int f = idx & 31, bt = idx >> 5;
    float v = (f < F0) ? x[(size_t)bt * F0 + f] : 0.f;
    __half h = __float2half(v);
    xh[idx] = h;
    xl[idx] = __float2half(v - __half2float(h));
}

// fold prev BN into weights, reorder k'=j*Cpad+c, fp16 hi/lo split
__global__ void fold_split(const float* __restrict__ w, const float* __restrict__ bias,
                           const float* __restrict__ mean, const float* __restrict__ istd,
                           const float* __restrict__ g, const float* __restrict__ be,
                           __half* __restrict__ wh, __half* __restrict__ wl, float* __restrict__ bp,
                           int Korig, int NOFF, int C, int Cpad, int Cout, int Kp) {
    int o = blockIdx.x;
    float part = 0.f;
    for (int k = threadIdx.x; k < Kp; k += 256) {
        int j = k / Cpad, c = k - j * Cpad;
        float wa = 0.f;
        if (o < Cout && c < C) {
            float a = 1.f, d = 0.f;
            if (mean) { a = istd[c] * (g ? g[c] : 1.f); d = (be ? be[c] : 0.f) - mean[c] * a; }
            float wv = w[(size_t)o * Korig + c * NOFF + j];
            wa = wv * a;
            part += wv * d;
        }
        __half h = __float2half(wa);
        wh[(size_t)o * Kp + k] = h;
        wl[(size_t)o * Kp + k] = __float2half(wa - __half2float(h));
    }
    __shared__ float sh[256];
    sh[threadIdx.x] = part;
    __syncthreads();
    for (int d2 = 128; d2 > 0; d2 >>= 1) {
        if (threadIdx.x < d2) sh[threadIdx.x] += sh[threadIdx.x + d2];
        __syncthreads();
    }
    if (threadIdx.x == 0) bp[o] = (o < Cout ? bias[o] : 0.f) + sh[0];
}

// -------------------------- mma.sync GEMM -----------------------------------
// CTA 128x128, BK=32, 8 warps (4m x 2n), warp 32x64, fp16 hi/lo 3-term.
// 2-stage cp.async pipeline (2x40960B smem -> 2 CTAs/SM).
__global__ __launch_bounds__(256, 2)
void mma_gemm(const __half* __restrict__ Ah, const __half* __restrict__ Al,
              const __half* __restrict__ Wh, const __half* __restrict__ Wl,
              const float* __restrict__ bias,
              __half* __restrict__ Oh, __half* __restrict__ Ol,
              float* __restrict__ Ps, float* __restrict__ Pq,
              int Tin, int Tout, int Cpad, int step, int Kp, int Coutp, int act) {
    extern __shared__ char smem[];
    uint32_t su = s2u(smem);
    int tid = threadIdx.x, lane = tid & 31, wid = tid >> 5;
    int b = blockIdx.z, t0 = blockIdx.x * 128, obase = blockIdx.y * 128;
    int wm = wid >> 1, wn = wid & 1;
    int nk = Kp >> 5;

    float acc[2][8][4];
#pragma unroll
    for (int i = 0; i < 2; i++)
#pragma unroll
        for (int j = 0; j < 8; j++)
#pragma unroll
            for (int q = 0; q < 4; q++) acc[i][j][q] = 0.f;

    auto load_stage = [&](int buf, int kc) {
        int kc0 = kc << 5;
        int j = kc0 / Cpad, c0 = kc0 - j * Cpad, off = j * step;
        uint32_t sb = su + buf * 40960;
        const __half* pa[2] = {Ah, Al};
        const __half* pw[2] = {Wh, Wl};
#pragma unroll
        for (int h = 0; h < 2; h++) {
#pragma unroll
            for (int i = 0; i < 2; i++) {
                int e = tid + i * 256, r = e >> 2, c = e & 3;
                cpa16(sb + h * 10240 + r * 80 + c * 16,
                      pa[h] + ((size_t)b * Tin + t0 + off + r) * Cpad + c0 + c * 8,
                      (t0 + r < Tout) ? 16 : 0);
            }
#pragma unroll
            for (int i = 0; i < 2; i++) {
                int e = tid + i * 256, r = e >> 2, c = e & 3;
                cpa16(sb + 20480 + h * 10240 + r * 80 + c * 16,
                      pw[h] + ((size_t)(obase + r)) * Kp + kc0 + c * 8, 16);
            }
        }
        CP_COMMIT();
    };

    auto compute = [&](int buf) {
        uint32_t sb = su + buf * 40960;
#pragma unroll
        for (int ks = 0; ks < 2; ks++) {
            uint32_t ah[2][4], al[2][4];
#pragma unroll
            for (int mf = 0; mf < 2; mf++) {
                int row = wm * 32 + mf * 16 + (lane & 15);
                uint32_t addr = sb + row * 80 + (ks * 16 + ((lane >> 4) << 3)) * 2;
                ldm_x4(ah[mf], addr);
                ldm_x4(al[mf], addr + 10240);
            }
#pragma unroll
            for (int nb = 0; nb < 2; nb++) {
                uint32_t bh[4][2], bl[4][2];
#pragma unroll
                for (int qq = 0; qq < 2; qq++) {
                    int g = lane >> 3;
                    int rowb = wn * 64 + nb * 32 + qq * 16 + ((g >> 1) << 3) + (lane & 7);
                    uint32_t addr = sb + 20480 + rowb * 80 + (ks * 16 + ((g & 1) << 3)) * 2;
                    uint32_t th[4], tl[4];
                    ldm_x4(th, addr);
                    ldm_x4(tl, addr + 10240);
                    bh[qq * 2][0] = th[0]; bh[qq * 2][1] = th[1];
                    bh[qq * 2 + 1][0] = th[2]; bh[qq * 2 + 1][1] = th[3];
                    bl[qq * 2][0] = tl[0]; bl[qq * 2][1] = tl[1];
                    bl[qq * 2 + 1][0] = tl[2]; bl[qq * 2 + 1][1] = tl[3];
                }
#pragma unroll
                for (int mf = 0; mf < 2; mf++)
#pragma unroll
                    for (int q = 0; q < 4; q++) {
                        int nf = nb * 4 + q;
                        mma16816(acc[mf][nf], ah[mf], bh[q]);
                        mma16816(acc[mf][nf], ah[mf], bl[q]);
                        mma16816(acc[mf][nf], al[mf], bh[q]);
                    }
            }
        }
    };

    load_stage(0, 0);
    load_stage(1, 1);
    for (int kc = 0; kc < nk; kc++) {
        if (kc < nk - 2) CP_WAIT1(); else CP_WAIT0();
        __syncthreads();
        compute(kc & 1);
        __syncthreads();
        if (kc + 2 < nk) load_stage(kc & 1, kc + 2);
    }

    // ------- fused epilogue: activations + column stats -------
    int l4 = lane >> 2, l2 = (lane & 3) << 1;
    float s_[8][2] = {}, q_[8][2] = {};
#pragma unroll
    for (int mf = 0; mf < 2; mf++)
#pragma unroll
        for (int hh = 0; hh < 2; hh++) {
            int t = t0 + wm * 32 + mf * 16 + l4 + hh * 8;
            bool tv = t < Tout;
            size_t ro = ((size_t)b * Tout + t) * Coutp + obase + wn * 64;
#pragma unroll
            for (int nf = 0; nf < 8; nf++) {
                int o = nf * 8 + l2;
                float v0 = acc[mf][nf][hh * 2 + 0] + bias[obase + wn * 64 + o];
                float v1 = acc[mf][nf][hh * 2 + 1] + bias[obase + wn * 64 + o + 1];
                v0 = fmaxf(v0, 0.f); v1 = fmaxf(v1, 0.f);
                if (act) { v0 = fminf(v0, 6.f); v1 = fminf(v1, 6.f); }
                if (tv) {
                    s_[nf][0] += v0; q_[nf][0] += v0 * v0;
                    s_[nf][1] += v1; q_[nf][1] += v1 * v1;
                    if (Oh) {
                        __half h0 = __float2half(v0), h1 = __float2half(v1);
                        *(__half2*)(Oh + ro + o) = __halves2half2(h0, h1);
                        *(__half2*)(Ol + ro + o) = __halves2half2(
                            __float2half(v0 - __half2float(h0)), __float2half(v1 - __half2float(h1)));
                    }
                }
            }
        }
    if (Ps) {
#pragma unroll
        for (int nf = 0; nf < 8; nf++)
#pragma unroll
            for (int e = 0; e < 2; e++)
#pragma unroll
                for (int o = 4; o <= 16; o <<= 1) {
                    s_[nf][e] += __shfl_xor_sync(0xffffffffu, s_[nf][e], o);
                    q_[nf][e] += __shfl_xor_sync(0xffffffffu, q_[nf][e], o);
                }
        float* ss = (float*)smem;
        float* sq = ss + 128;
        __syncthreads();
        if (tid < 256) ss[tid] = 0.f;
        __syncthreads();
        if ((lane >> 2) == 0) {
#pragma unroll
            for (int nf = 0; nf < 8; nf++)
#pragma unroll
                for (int e = 0; e < 2; e++) {
                    int col = wn * 64 + nf * 8 + (lane & 3) * 2 + e;
                    atomicAdd(&ss[col], s_[nf][e]);
                    atomicAdd(&sq[col], q_[nf][e]);
                }
        }
        __syncthreads();
        if (tid < 128) {
            size_t pidx = ((size_t)blockIdx.x * BB + b) * Coutp + obase + tid;
            Ps[pidx] = ss[tid];
            Pq[pidx] = sq[tid];
        }
    }
}

// --------------------------- stats / tail -----------------------------------
// two-stage reduce of NSL=512 partial slices (L1-4)
__global__ void statfin1(const float* __restrict__ ps, const float* __restrict__ pq,
                         float* __restrict__ pm, float* __restrict__ qm, int Cpad) {
    int c = blockIdx.x * 256 + threadIdx.x;
    int g = blockIdx.y;
    float s = 0.f, q = 0.f;
    for (int i = g * 32; i < g * 32 + 32; i++) {
        s += ps[(size_t)i * Cpad + c];
        q += pq[(size_t)i * Cpad + c];
    }
    pm[(size_t)g * Cpad + c] = s;
    qm[(size_t)g * Cpad + c] = q;
}
__global__ void statfin2(const float* __restrict__ pm, const float* __restrict__ qm,
                         float* __restrict__ mean, float* __restrict__ istd, int Cpad, float N) {
    int c = blockIdx.x * 256 + threadIdx.x;
    if (c >= Cpad) return;
    float s = 0.f, q = 0.f;
    for (int i = 0; i < 16; i++) { s += pm[(size_t)i * Cpad + c]; q += qm[(size_t)i * Cpad + c]; }
    float m = s / N;
    mean[c] = m;
    istd[c] = rsqrtf(q / N - m * m + EPSF);
}
__global__ void part5reduce(const float* __restrict__ ps, const float* __restrict__ pq,
                            float* __restrict__ rsum, float* __restrict__ rsq) {
    int c = blockIdx.x * 256 + threadIdx.x;
    int b = blockIdx.y;
    if (c >= C5) return;
    float s = 0.f, q = 0.f;
    for (int i = 0; i < 16; i++) {
        s += ps[((size_t)i * BB + b) * C5P + c];
        q += pq[((size_t)i * BB + b) * C5P + c];
    }
    rsum[b * C5 + c] = s;
    rsq[b * C5 + c] = q;
}
__global__ void chstats5(const float* __restrict__ rsum, const float* __restrict__ rsq,
                         float* __restrict__ mean, float* __restrict__ istd) {
    int c = blockIdx.x * 256 + threadIdx.x;
    if (c >= C5) return;
    float s = 0.f, ss = 0.f;
    for (int b = 0; b < BB; b++) { s += rsum[b * C5 + c]; ss += rsq[b * C5 + c]; }
    float N = (float)BB * (float)T5;
    float m = s / N;
    mean[c] = m;
    istd[c] = rsqrtf(ss / N - m * m + EPSF);
}
__global__ void pool_kernel(const float* __restrict__ rsum, const float* __restrict__ rsq,
                            const float* __restrict__ m5, const float* __restrict__ i5,
                            const float* __restrict__ g5, const float* __restrict__ be5,
                            float* __restrict__ pooled) {
    int idx = blockIdx.x * 256 + threadIdx.x;
    if (idx >= BB * C5) return;
    int c = idx % C5, b = idx / C5;
    float Tf = (float)T5;
    float mt = rsum[b * C5 + c] / Tf;
    float vart = (rsq[b * C5 + c] - Tf * mt * mt) / (Tf - 1.f);
    float a = i5[c] * g5[c];
    float d = be5[c] - m5[c] * a;
    pooled[(size_t)b * 3000 + c] = a * mt + d;
    pooled[(size_t)b * 3000 + 1500 + c] = fabsf(a) * sqrtf(fmaxf(vart, 0.f));
}
__global__ void fc_kernel(const float* __restrict__ in, const float* __restrict__ w,
                          const float* __restrict__ bias, float* __restrict__ out, int K, int Cout) {
    int o = blockIdx.x, b = blockIdx.y;
    const float* ir = in + (size_t)b * K;
    const float* wr = w + (size_t)o * K;
    float s = 0.f;
    for (int k = threadIdx.x; k < K; k += 128) s += ir[k] * wr[k];
    __shared__ float sh[128];
    sh[threadIdx.x] = s;
    __syncthreads();
    for (int d = 64; d > 0; d >>= 1) {
        if (threadIdx.x < d) sh[threadIdx.x] += sh[threadIdx.x + d];
        __syncthreads();
    }
    if (threadIdx.x == 0) out[(size_t)b * Cout + o] = fminf(fmaxf(sh[0] + bias[o], 0.f), 6.f);
}
__global__ void bnc_kernel(const float* __restrict__ z, const float* __restrict__ g,
                           const float* __restrict__ be, float* __restrict__ out, int C) {
    int c = threadIdx.x + blockIdx.x * 256;
    if (c >= C) return;
    float s = 0.f, ss = 0.f;
    for (int b = 0; b < BB; b++) { float v = z[(size_t)b * C + c]; s += v; ss += v * v; }
    float m = s / (float)BB;
    float is = rsqrtf(ss / (float)BB - m * m + EPSF);
    for (int b = 0; b < BB; b++)
        out[(size_t)b * C + c] = (z[(size_t)b * C + c] - m) * is * g[c] + be[c];
}

// ------------------------------- host ---------------------------------------
static void* sa(const void* sym) { void* p = nullptr; cudaGetSymbolAddress(&p, sym); return p; }

extern "C" void kernel_launch(void* const* d_in, const int* in_sizes, int n_in,
                              void* d_out, int out_size) {
    const float* x = (const float*)d_in[0];
    const float *h1w = (const float*)d_in[1], *h1b = (const float*)d_in[2];
    const float *h2w = (const float*)d_in[3], *h2b = (const float*)d_in[4];
    const float *bn2g = (const float*)d_in[5], *bn2b = (const float*)d_in[6];
    const float *h3w = (const float*)d_in[7], *h3b = (const float*)d_in[8];
    const float *bn3g = (const float*)d_in[9], *bn3b = (const float*)d_in[10];
    const float *h4w = (const float*)d_in[11], *h4b = (const float*)d_in[12];
    const float *bn4g = (const float*)d_in[13], *bn4b = (const float*)d_in[14];
    const float *h5w = (const float*)d_in[15], *h5b = (const float*)d_in[16];
    const float *bn5g = (const float*)d_in[17], *bn5b = (const float*)d_in[18];
    const float *l1w = (const float*)d_in[19], *l1b = (const float*)d_in[20];
    const float *bn6g = (const float*)d_in[21], *bn6b = (const float*)d_in[22];
    const float *l2w = (const float*)d_in[23], *l2b = (const float*)d_in[24];
    const float *bn7g = (const float*)d_in[25], *bn7b = (const float*)d_in[26];

    __half *xh = (__half*)sa(g_xhi), *xl = (__half*)sa(g_xlo);
    __half *a1h = (__half*)sa(g_a1hi), *a1l = (__half*)sa(g_a1lo);
    __half *a2h = (__half*)sa(g_a2hi), *a2l = (__half*)sa(g_a2lo);
    __half *a3h = (__half*)sa(g_a3hi), *a3l = (__half*)sa(g_a3lo);
    __half *a4h = (__half*)sa(g_a4hi), *a4l = (__half*)sa(g_a4lo);
    __half *w1h = (__half*)sa(g_w1hi), *w1l = (__half*)sa(g_w1lo);
    __half *w2h = (__half*)sa(g_w2hi), *w2l = (__half*)sa(g_w2lo);
    __half *w3h = (__half*)sa(g_w3hi), *w3l = (__half*)sa(g_w3lo);
    __half *w4h = (__half*)sa(g_w4hi), *w4l = (__half*)sa(g_w4lo);
    __half *w5h = (__half*)sa(g_w5hi), *w5l = (__half*)sa(g_w5lo);
    float *b1 = (float*)sa(g_b1p), *b2 = (float*)sa(g_b2p), *b3 = (float*)sa(g_b3p);
    float *b4 = (float*)sa(g_b4p), *b5 = (float*)sa(g_b5p);
    float *ps = (float*)sa(g_ps), *pq = (float*)sa(g_pq);
    float *pm = (float*)sa(g_pm), *qm = (float*)sa(g_qm);
    float *p5s = (float*)sa(g_p5s), *p5q = (float*)sa(g_p5q);
    float *m1 = (float*)sa(g_m1), *i1 = (float*)sa(g_i1), *m2 = (float*)sa(g_m2), *i2 = (float*)sa(g_i2);
    float *m3 = (float*)sa(g_m3), *i3 = (float*)sa(g_i3), *m4 = (float*)sa(g_m4), *i4 = (float*)sa(g_i4);
    float *m5 = (float*)sa(g_m5), *i5 = (float*)sa(g_i5);
    float *rsum = (float*)sa(g_rsum), *rsq = (float*)sa(g_rsq), *pool = (float*)sa(g_pool);
    float *z1 = (float*)sa(g_z1), *u1 = (float*)sa(g_u1), *z2 = (float*)sa(g_z2);

    const int SMEMB = 2 * 40960;
    cudaFuncSetAttribute(mma_gemm, cudaFuncAttributeMaxDynamicSharedMemorySize, SMEMB);

    xsplit<<<(BB * T0 * 32 + 255) / 256, 256>>>(x, xh, xl);

    // L1: K'=160 (5 offset blocks, Cpad=32), step 1, relu; stats fused
    fold_split<<<512, 256>>>(h1w, h1b, nullptr, nullptr, nullptr, nullptr, w1h, w1l, b1, 100, 5, 20, 32, 512, 160);
    mma_gemm<<<dim3(16, 4, BB), 256, SMEMB>>>(xh, xl, w1h, w1l, b1, a1h, a1l, ps, pq, T0, T1, 32, 1, 160, 512, 0);
    statfin1<<<dim3(2, 16), 256>>>(ps, pq, pm, qm, 512);
    statfin2<<<2, 256>>>(pm, qm, m1, i1, 512, (float)BB * (float)T1);

    // L2: fold bn1, offsets {0,2,4}, relu; stats fused
    fold_split<<<512, 256>>>(h2w, h2b, m1, i1, nullptr, nullptr, w2h, w2l, b2, 1536, 3, 512, 512, 512, 1536);
    mma_gemm<<<dim3(16, 4, BB), 256, SMEMB>>>(a1h, a1l, w2h, w2l, b2, a2h, a2l, ps, pq, T1, T2, 512, 2, 1536, 512, 0);
    statfin1<<<dim3(2, 16), 256>>>(ps, pq, pm, qm, 512);
    statfin2<<<2, 256>>>(pm, qm, m2, i2, 512, (float)BB * (float)T2);

    // L3: fold bn2, offsets {0,3,6}, relu; stats fused
    fold_split<<<512, 256>>>(h3w, h3b, m2, i2, bn2g, bn2b, w3h, w3l, b3, 1536, 3, 512, 512, 512, 1536);
    mma_gemm<<<dim3(16, 4, BB), 256, SMEMB>>>(a2h, a2l, w3h, w3l, b3, a3h, a3l, ps, pq, T2, T3, 512, 3, 1536, 512, 0);
    statfin1<<<dim3(2, 16), 256>>>(ps, pq, pm, qm, 512);
    statfin2<<<2, 256>>>(pm, qm, m3, i3, 512, (float)BB * (float)T3);

    // L4: fold bn3, 512->512, relu6; stats fused
    fold_split<<<512, 256>>>(h4w, h4b, m3, i3, bn3g, bn3b, w4h, w4l, b4, 512, 1, 512, 512, 512, 512);
    mma_gemm<<<dim3(16, 4, BB), 256, SMEMB>>>(a3h, a3l, w4h, w4l, b4, a4h, a4l, ps, pq, T3, T3, 512, 0, 512, 512, 1);
    statfin1<<<dim3(2, 16), 256>>>(ps, pq, pm, qm, 512);
    statfin2<<<2, 256>>>(pm, qm, m4, i4, 512, (float)BB * (float)T3);

    // L5: fold bn4, 512->1500 (pad 1536), relu6; stats-only epilogue
    fold_split<<<C5P, 256>>>(h5w, h5b, m4, i4, bn4g, bn4b, w5h, w5l, b5, 512, 1, 512, 512, C5, 512);
    mma_gemm<<<dim3(16, 12, BB), 256, SMEMB>>>(a4h, a4l, w5h, w5l, b5, nullptr, nullptr, p5s, p5q, T3, T5, 512, 0, 512, C5P, 1);

    // stats pooling (bn5 folded analytically)
    part5reduce<<<dim3(6, BB), 256>>>(p5s, p5q, rsum, rsq);
    chstats5<<<6, 256>>>(rsum, rsq, m5, i5);
    pool_kernel<<<(BB * C5 + 255) / 256, 256>>>(rsum, rsq, m5, i5, bn5g, bn5b, pool);

    // tail FCs
    fc_kernel<<<dim3(512, BB), 128>>>(pool, l1w, l1b, z1, 3000, 512);
    bnc_kernel<<<2, 256>>>(z1, bn6g, bn6b, u1, 512);
    fc_kernel<<<dim3(512, BB), 128>>>(u1, l2w, l2b, z2, 512, 512);
    bnc_kernel<<<2, 256>>>(z2, bn7g, bn7b, (float*)d_out, 512);
}

// round 12
// speedup vs baseline: 1.9711x; 1.0184x over previous
#include <cuda_runtime.h>
#include <cuda_fp16.h>
#include <cstdint>
#include <cstddef>

#define EPSF 1e-5f
constexpr int BB = 32, F0 = 20, T0 = 2048;
constexpr int T1 = 2044, T2 = 2040, T3 = 2034, T5 = 2034;
constexpr int C5 = 1500, C5P = 1536;
constexpr int NSL = 512;

// ------------------------------- scratch -----------------------------------
__device__ __align__(16) __half g_xhi[(size_t)BB * T0 * 32],  g_xlo[(size_t)BB * T0 * 32];
__device__ __align__(16) __half g_a1hi[(size_t)BB * T1 * 512], g_a1lo[(size_t)BB * T1 * 512];
__device__ __align__(16) __half g_a2hi[(size_t)BB * T2 * 512], g_a2lo[(size_t)BB * T2 * 512];
__device__ __align__(16) __half g_a3hi[(size_t)BB * T3 * 512], g_a3lo[(size_t)BB * T3 * 512];
__device__ __align__(16) __half g_a4hi[(size_t)BB * T3 * 512], g_a4lo[(size_t)BB * T3 * 512];
__device__ __align__(16) __half g_w1hi[512 * 160],  g_w1lo[512 * 160];
__device__ __align__(16) __half g_w2hi[512 * 1536], g_w2lo[512 * 1536];
__device__ __align__(16) __half g_w3hi[512 * 1536], g_w3lo[512 * 1536];
__device__ __align__(16) __half g_w4hi[512 * 512],  g_w4lo[512 * 512];
__device__ __align__(16) __half g_w5hi[C5P * 512];
__device__ float g_b1p[512], g_b2p[512], g_b3p[512], g_b4p[512], g_b5p[C5P];
__device__ float g_ps[NSL * 512], g_pq[NSL * 512];
__device__ float g_pm[16 * 512], g_qm[16 * 512];
__device__ float g_p5s[16 * BB * C5P], g_p5q[16 * BB * C5P];
__device__ float g_m1[512], g_i1[512], g_m2[512], g_i2[512];
__device__ float g_m3[512], g_i3[512], g_m4[512], g_i4[512];
__device__ float g_m5[C5], g_i5[C5];
__device__ float g_rsum[BB * C5], g_rsq[BB * C5];
__device__ float g_pool[BB * 3000];
__device__ float g_z1[BB * 512], g_u1[BB * 512], g_z2[BB * 512];

// ----------------------------- helpers --------------------------------------
__device__ __forceinline__ uint32_t s2u(const void* p) {
    uint32_t a;
    asm("{ .reg .u64 t; cvta.to.shared.u64 t, %1; cvt.u32.u64 %0, t; }" : "=r"(a) : "l"(p));
    return a;
}
__device__ __forceinline__ void ldm_x4(uint32_t a[4], uint32_t addr) {
    asm volatile("ldmatrix.sync.aligned.m8n8.x4.shared.b16 {%0,%1,%2,%3}, [%4];"
                 : "=r"(a[0]), "=r"(a[1]), "=r"(a[2]), "=r"(a[3]) : "r"(addr));
}
__device__ __forceinline__ void mma16816(float c[4], const uint32_t a[4], const uint32_t b[2]) {
    asm volatile("mma.sync.aligned.m16n8k16.row.col.f32.f16.f16.f32 "
                 "{%0,%1,%2,%3}, {%4,%5,%6,%7}, {%8,%9}, {%0,%1,%2,%3};"
                 : "+f"(c[0]), "+f"(c[1]), "+f"(c[2]), "+f"(c[3])
                 : "r"(a[0]), "r"(a[1]), "r"(a[2]), "r"(a[3]), "r"(b[0]), "r"(b[1]));
}
__device__ __forceinline__ void cpa16(uint32_t dst, const void* src, int sz) {
    asm volatile("cp.async.ca.shared.global [%0], [%1], 16, %2;" :: "r"(dst), "l"(src), "r"(sz));
}
#define CP_COMMIT() asm volatile("cp.async.commit_group;" ::: "memory")
#define CP_WAIT1() asm volatile("cp.async.wait_group 1;" ::: "memory")
#define CP_WAIT0() asm volatile("cp.async.wait_group 0;" ::: "memory")

// ------------------------------ prep kernels --------------------------------
__global__ void xsplit(const float* __restrict__ x, __half* __restrict__ xh, __half* __restrict__ xl) {
    int idx = blockIdx.x * 256 + threadIdx.x;
    if (idx >= BB * T0 * 32) return;
    int f = idx & 31, bt = idx >> 5;
    float v = (f < F0) ? x[(size_t)bt * F0 + f] : 0.f;
    __half h = __float2half(v);
    xh[idx] = h;
    xl[idx] = __float2half(v - __half2float(h));
}

// fold prev BN into weights, reorder k'=j*Cpad+c, fp16 hi/(optional lo) split
__global__ void fold_split(const float* __restrict__ w, const float* __restrict__ bias,
                           const float* __restrict__ mean, const float* __restrict__ istd,
                           const float* __restrict__ g, const float* __restrict__ be,
                           __half* __restrict__ wh, __half* __restrict__ wl, float* __restrict__ bp,
                           int Korig, int NOFF, int C, int Cpad, int Cout, int Kp) {
    int o = blockIdx.x;
    float part = 0.f;
    for (int k = threadIdx.x; k < Kp; k += 256) {
        int j = k / Cpad, c = k - j * Cpad;
        float wa = 0.f;
        if (o < Cout && c < C) {
            float a = 1.f, d = 0.f;
            if (mean) { a = istd[c] * (g ? g[c] : 1.f); d = (be ? be[c] : 0.f) - mean[c] * a; }
            float wv = w[(size_t)o * Korig + c * NOFF + j];
            wa = wv * a;
            part += wv * d;
        }
        __half h = __float2half(wa);
        wh[(size_t)o * Kp + k] = h;
        if (wl) wl[(size_t)o * Kp + k] = __float2half(wa - __half2float(h));
    }
    __shared__ float sh[256];
    sh[threadIdx.x] = part;
    __syncthreads();
    for (int d2 = 128; d2 > 0; d2 >>= 1) {
        if (threadIdx.x < d2) sh[threadIdx.x] += sh[threadIdx.x + d2];
        __syncthreads();
    }
    if (threadIdx.x == 0) bp[o] = (o < Cout ? bias[o] : 0.f) + sh[0];
}

// -------------------------- mma.sync GEMM -----------------------------------
// CTA 128x128, BK=32, 8 warps (4m x 2n), warp 32x64, fp16 hi/lo.
// Wl != nullptr: 3-term (AhWh + AhWl + AlWh); Wl == nullptr: 2-term (AhWh + AlWh).
// 2-stage cp.async pipeline (2x40960B smem -> 2 CTAs/SM).
__global__ __launch_bounds__(256, 2)
void mma_gemm(const __half* __restrict__ Ah, const __half* __restrict__ Al,
              const __half* __restrict__ Wh, const __half* __restrict__ Wl,
              const float* __restrict__ bias,
              __half* __restrict__ Oh, __half* __restrict__ Ol,
              float* __restrict__ Ps, float* __restrict__ Pq,
              int Tin, int Tout, int Cpad, int step, int Kp, int Coutp, int act) {
    extern __shared__ char smem[];
    uint32_t su = s2u(smem);
    int tid = threadIdx.x, lane = tid & 31, wid = tid >> 5;
    int b = blockIdx.z, t0 = blockIdx.x * 128, obase = blockIdx.y * 128;
    int wm = wid >> 1, wn = wid & 1;
    int nk = Kp >> 5;
    bool uwl = (Wl != nullptr);

    float acc[2][8][4];
#pragma unroll
    for (int i = 0; i < 2; i++)
#pragma unroll
        for (int j = 0; j < 8; j++)
#pragma unroll
            for (int q = 0; q < 4; q++) acc[i][j][q] = 0.f;

    auto load_stage = [&](int buf, int kc) {
        int kc0 = kc << 5;
        int j = kc0 / Cpad, c0 = kc0 - j * Cpad, off = j * step;
        uint32_t sb = su + buf * 40960;
        const __half* pa[2] = {Ah, Al};
#pragma unroll
        for (int h = 0; h < 2; h++) {
#pragma unroll
            for (int i = 0; i < 2; i++) {
                int e = tid + i * 256, r = e >> 2, c = e & 3;
                cpa16(sb + h * 10240 + r * 80 + c * 16,
                      pa[h] + ((size_t)b * Tin + t0 + off + r) * Cpad + c0 + c * 8,
                      (t0 + r < Tout) ? 16 : 0);
            }
        }
#pragma unroll
        for (int i = 0; i < 2; i++) {
            int e = tid + i * 256, r = e >> 2, c = e & 3;
            cpa16(sb + 20480 + r * 80 + c * 16,
                  Wh + ((size_t)(obase + r)) * Kp + kc0 + c * 8, 16);
        }
        if (uwl) {
#pragma unroll
            for (int i = 0; i < 2; i++) {
                int e = tid + i * 256, r = e >> 2, c = e & 3;
                cpa16(sb + 30720 + r * 80 + c * 16,
                      Wl + ((size_t)(obase + r)) * Kp + kc0 + c * 8, 16);
            }
        }
        CP_COMMIT();
    };

    auto compute = [&](int buf) {
        uint32_t sb = su + buf * 40960;
#pragma unroll
        for (int ks = 0; ks < 2; ks++) {
            uint32_t ah[2][4], al[2][4];
#pragma unroll
            for (int mf = 0; mf < 2; mf++) {
                int row = wm * 32 + mf * 16 + (lane & 15);
                uint32_t addr = sb + row * 80 + (ks * 16 + ((lane >> 4) << 3)) * 2;
                ldm_x4(ah[mf], addr);
                ldm_x4(al[mf], addr + 10240);
            }
#pragma unroll
            for (int nb = 0; nb < 2; nb++) {
                uint32_t bh[4][2], bl[4][2];
#pragma unroll
                for (int qq = 0; qq < 2; qq++) {
                    int g = lane >> 3;
                    int rowb = wn * 64 + nb * 32 + qq * 16 + ((g >> 1) << 3) + (lane & 7);
                    uint32_t addr = sb + 20480 + rowb * 80 + (ks * 16 + ((g & 1) << 3)) * 2;
                    uint32_t th[4];
                    ldm_x4(th, addr);
                    bh[qq * 2][0] = th[0]; bh[qq * 2][1] = th[1];
                    bh[qq * 2 + 1][0] = th[2]; bh[qq * 2 + 1][1] = th[3];
                    if (uwl) {
                        uint32_t tl[4];
                        ldm_x4(tl, addr + 10240);
                        bl[qq * 2][0] = tl[0]; bl[qq * 2][1] = tl[1];
                        bl[qq * 2 + 1][0] = tl[2]; bl[qq * 2 + 1][1] = tl[3];
                    }
                }
#pragma unroll
                for (int mf = 0; mf < 2; mf++)
#pragma unroll
                    for (int q = 0; q < 4; q++) {
                        int nf = nb * 4 + q;
                        mma16816(acc[mf][nf], ah[mf], bh[q]);
                        mma16816(acc[mf][nf], al[mf], bh[q]);
                        if (uwl) mma16816(acc[mf][nf], ah[mf], bl[q]);
                    }
            }
        }
    };

    load_stage(0, 0);
    load_stage(1, 1);
    for (int kc = 0; kc < nk; kc++) {
        if (kc < nk - 2) CP_WAIT1(); else CP_WAIT0();
        __syncthreads();
        compute(kc & 1);
        __syncthreads();
        if (kc + 2 < nk) load_stage(kc & 1, kc + 2);
    }

    // ------- fused epilogue: activations + column stats -------
    int l4 = lane >> 2, l2 = (lane & 3) << 1;
    float s_[8][2] = {}, q_[8][2] = {};
#pragma unroll
    for (int mf = 0; mf < 2; mf++)
#pragma unroll
        for (int hh = 0; hh < 2; hh++) {
            int t = t0 + wm * 32 + mf * 16 + l4 + hh * 8;
            bool tv = t < Tout;
            size_t ro = ((size_t)b * Tout + t) * Coutp + obase + wn * 64;
#pragma unroll
            for (int nf = 0; nf < 8; nf++) {
                int o = nf * 8 + l2;
                float v0 = acc[mf][nf][hh * 2 + 0] + bias[obase + wn * 64 + o];
                float v1 = acc[mf][nf][hh * 2 + 1] + bias[obase + wn * 64 + o + 1];
                v0 = fmaxf(v0, 0.f); v1 = fmaxf(v1, 0.f);
                if (act) { v0 = fminf(v0, 6.f); v1 = fminf(v1, 6.f); }
                if (tv) {
                    s_[nf][0] += v0; q_[nf][0] += v0 * v0;
                    s_[nf][1] += v1; q_[nf][1] += v1 * v1;
                    if (Oh) {
                        __half h0 = __float2half(v0), h1 = __float2half(v1);
                        *(__half2*)(Oh + ro + o) = __halves2half2(h0, h1);
                        *(__half2*)(Ol + ro + o) = __halves2half2(
                            __float2half(v0 - __half2float(h0)), __float2half(v1 - __half2float(h1)));
                    }
                }
            }
        }
    if (Ps) {
#pragma unroll
        for (int nf = 0; nf < 8; nf++)
#pragma unroll
            for (int e = 0; e < 2; e++)
#pragma unroll
                for (int o = 4; o <= 16; o <<= 1) {
                    s_[nf][e] += __shfl_xor_sync(0xffffffffu, s_[nf][e], o);
                    q_[nf][e] += __shfl_xor_sync(0xffffffffu, q_[nf][e], o);
                }
        float* ss = (float*)smem;
        float* sq = ss + 128;
        __syncthreads();
        if (tid < 256) ss[tid] = 0.f;
        __syncthreads();
        if ((lane >> 2) == 0) {
#pragma unroll
            for (int nf = 0; nf < 8; nf++)
#pragma unroll
                for (int e = 0; e < 2; e++) {
                    int col = wn * 64 + nf * 8 + (lane & 3) * 2 + e;
                    atomicAdd(&ss[col], s_[nf][e]);
                    atomicAdd(&sq[col], q_[nf][e]);
                }
        }
        __syncthreads();
        if (tid < 128) {
            size_t pidx = ((size_t)blockIdx.x * BB + b) * Coutp + obase + tid;
            Ps[pidx] = ss[tid];
            Pq[pidx] = sq[tid];
        }
    }
}

// --------------------------- stats / tail -----------------------------------
__global__ void statfin1(const float* __restrict__ ps, const float* __restrict__ pq,
                         float* __restrict__ pm, float* __restrict__ qm, int Cpad) {
    int c = blockIdx.x * 256 + threadIdx.x;
    int g = blockIdx.y;
    float s = 0.f, q = 0.f;
    for (int i = g * 32; i < g * 32 + 32; i++) {
        s += ps[(size_t)i * Cpad + c];
        q += pq[(size_t)i * Cpad + c];
    }
    pm[(size_t)g * Cpad + c] = s;
    qm[(size_t)g * Cpad + c] = q;
}
__global__ void statfin2(const float* __restrict__ pm, const float* __restrict__ qm,
                         float* __restrict__ mean, float* __restrict__ istd, int Cpad, float N) {
    int c = blockIdx.x * 256 + threadIdx.x;
    if (c >= Cpad) return;
    float s = 0.f, q = 0.f;
    for (int i = 0; i < 16; i++) { s += pm[(size_t)i * Cpad + c]; q += qm[(size_t)i * Cpad + c]; }
    float m = s / N;
    mean[c] = m;
    istd[c] = rsqrtf(q / N - m * m + EPSF);
}
__global__ void part5reduce(const float* __restrict__ ps, const float* __restrict__ pq,
                            float* __restrict__ rsum, float* __restrict__ rsq) {
    int c = blockIdx.x * 256 + threadIdx.x;
    int b = blockIdx.y;
    if (c >= C5) return;
    float s = 0.f, q = 0.f;
    for (int i = 0; i < 16; i++) {
        s += ps[((size_t)i * BB + b) * C5P + c];
        q += pq[((size_t)i * BB + b) * C5P + c];
    }
    rsum[b * C5 + c] = s;
    rsq[b * C5 + c] = q;
}
__global__ void chstats5(const float* __restrict__ rsum, const float* __restrict__ rsq,
                         float* __restrict__ mean, float* __restrict__ istd) {
    int c = blockIdx.x * 256 + threadIdx.x;
    if (c >= C5) return;
    float s = 0.f, ss = 0.f;
    for (int b = 0; b < BB; b++) { s += rsum[b * C5 + c]; ss += rsq[b * C5 + c]; }
    float N = (float)BB * (float)T5;
    float m = s / N;
    mean[c] = m;
    istd[c] = rsqrtf(ss / N - m * m + EPSF);
}
__global__ void pool_kernel(const float* __restrict__ rsum, const float* __restrict__ rsq,
                            const float* __restrict__ m5, const float* __restrict__ i5,
                            const float* __restrict__ g5, const float* __restrict__ be5,
                            float* __restrict__ pooled) {
    int idx = blockIdx.x * 256 + threadIdx.x;
    if (idx >= BB * C5) return;
    int c = idx % C5, b = idx / C5;
    float Tf = (float)T5;
    float mt = rsum[b * C5 + c] / Tf;
    float vart = (rsq[b * C5 + c] - Tf * mt * mt) / (Tf - 1.f);
    float a = i5[c] * g5[c];
    float d = be5[c] - m5[c] * a;
    pooled[(size_t)b * 3000 + c] = a * mt + d;
    pooled[(size_t)b * 3000 + 1500 + c] = fabsf(a) * sqrtf(fmaxf(vart, 0.f));
}
__global__ void fc_kernel(const float* __restrict__ in, const float* __restrict__ w,
                          const float* __restrict__ bias, float* __restrict__ out, int K, int Cout) {
    int o = blockIdx.x, b = blockIdx.y;
    const float* ir = in + (size_t)b * K;
    const float* wr = w + (size_t)o * K;
    float s = 0.f;
    for (int k = threadIdx.x; k < K; k += 128) s += ir[k] * wr[k];
    __shared__ float sh[128];
    sh[threadIdx.x] = s;
    __syncthreads();
    for (int d = 64; d > 0; d >>= 1) {
        if (threadIdx.x < d) sh[threadIdx.x] += sh[threadIdx.x + d];
        __syncthreads();
    }
    if (threadIdx.x == 0) out[(size_t)b * Cout + o] = fminf(fmaxf(sh[0] + bias[o], 0.f), 6.f);
}
__global__ void bnc_kernel(const float* __restrict__ z, const float* __restrict__ g,
                           const float* __restrict__ be, float* __restrict__ out, int C) {
    int c = threadIdx.x + blockIdx.x * 256;
    if (c >= C) return;
    float s = 0.f, ss = 0.f;
    for (int b = 0; b < BB; b++) { float v = z[(size_t)b * C + c]; s += v; ss += v * v; }
    float m = s / (float)BB;
    float is = rsqrtf(ss / (float)BB - m * m + EPSF);
    for (int b = 0; b < BB; b++)
        out[(size_t)b * C + c] = (z[(size_t)b * C + c] - m) * is * g[c] + be[c];
}

// ------------------------------- host ---------------------------------------
static void* sa(const void* sym) { void* p = nullptr; cudaGetSymbolAddress(&p, sym); return p; }

extern "C" void kernel_launch(void* const* d_in, const int* in_sizes, int n_in,
                              void* d_out, int out_size) {
    const float* x = (const float*)d_in[0];
    const float *h1w = (const float*)d_in[1], *h1b = (const float*)d_in[2];
    const float *h2w = (const float*)d_in[3], *h2b = (const float*)d_in[4];
    const float *bn2g = (const float*)d_in[5], *bn2b = (const float*)d_in[6];
    const float *h3w = (const float*)d_in[7], *h3b = (const float*)d_in[8];
    const float *bn3g = (const float*)d_in[9], *bn3b = (const float*)d_in[10];
    const float *h4w = (const float*)d_in[11], *h4b = (const float*)d_in[12];
    const float *bn4g = (const float*)d_in[13], *bn4b = (const float*)d_in[14];
    const float *h5w = (const float*)d_in[15], *h5b = (const float*)d_in[16];
    const float *bn5g = (const float*)d_in[17], *bn5b = (const float*)d_in[18];
    const float *l1w = (const float*)d_in[19], *l1b = (const float*)d_in[20];
    const float *bn6g = (const float*)d_in[21], *bn6b = (const float*)d_in[22];
    const float *l2w = (const float*)d_in[23], *l2b = (const float*)d_in[24];
    const float *bn7g = (const float*)d_in[25], *bn7b = (const float*)d_in[26];

    __half *xh = (__half*)sa(g_xhi), *xl = (__half*)sa(g_xlo);
    __half *a1h = (__half*)sa(g_a1hi), *a1l = (__half*)sa(g_a1lo);
    __half *a2h = (__half*)sa(g_a2hi), *a2l = (__half*)sa(g_a2lo);
    __half *a3h = (__half*)sa(g_a3hi), *a3l = (__half*)sa(g_a3lo);
    __half *a4h = (__half*)sa(g_a4hi), *a4l = (__half*)sa(g_a4lo);
    __half *w1h = (__half*)sa(g_w1hi), *w1l = (__half*)sa(g_w1lo);
    __half *w2h = (__half*)sa(g_w2hi), *w2l = (__half*)sa(g_w2lo);
    __half *w3h = (__half*)sa(g_w3hi), *w3l = (__half*)sa(g_w3lo);
    __half *w4h = (__half*)sa(g_w4hi), *w4l = (__half*)sa(g_w4lo);
    __half *w5h = (__half*)sa(g_w5hi);
    float *b1 = (float*)sa(g_b1p), *b2 = (float*)sa(g_b2p), *b3 = (float*)sa(g_b3p);
    float *b4 = (float*)sa(g_b4p), *b5 = (float*)sa(g_b5p);
    float *ps = (float*)sa(g_ps), *pq = (float*)sa(g_pq);
    float *pm = (float*)sa(g_pm), *qm = (float*)sa(g_qm);
    float *p5s = (float*)sa(g_p5s), *p5q = (float*)sa(g_p5q);
    float *m1 = (float*)sa(g_m1), *i1 = (float*)sa(g_i1), *m2 = (float*)sa(g_m2), *i2 = (float*)sa(g_i2);
    float *m3 = (float*)sa(g_m3), *i3 = (float*)sa(g_i3), *m4 = (float*)sa(g_m4), *i4 = (float*)sa(g_i4);
    float *m5 = (float*)sa(g_m5), *i5 = (float*)sa(g_i5);
    float *rsum = (float*)sa(g_rsum), *rsq = (float*)sa(g_rsq), *pool = (float*)sa(g_pool);
    float *z1 = (float*)sa(g_z1), *u1 = (float*)sa(g_u1), *z2 = (float*)sa(g_z2);

    const int SMEMB = 2 * 40960;
    cudaFuncSetAttribute(mma_gemm, cudaFuncAttributeMaxDynamicSharedMemorySize, SMEMB);

    xsplit<<<(BB * T0 * 32 + 255) / 256, 256>>>(x, xh, xl);

    // L1: K'=160 (5 offset blocks, Cpad=32), step 1, relu; 3-term; stats fused
    fold_split<<<512, 256>>>(h1w, h1b, nullptr, nullptr, nullptr, nullptr, w1h, w1l, b1, 100, 5, 20, 32, 512, 160);
    mma_gemm<<<dim3(16, 4, BB), 256, SMEMB>>>(xh, xl, w1h, w1l, b1, a1h, a1l, ps, pq, T0, T1, 32, 1, 160, 512, 0);
    statfin1<<<dim3(2, 16), 256>>>(ps, pq, pm, qm, 512);
    statfin2<<<2, 256>>>(pm, qm, m1, i1, 512, (float)BB * (float)T1);

    // L2: fold bn1, offsets {0,2,4}, relu; 3-term; stats fused
    fold_split<<<512, 256>>>(h2w, h2b, m1, i1, nullptr, nullptr, w2h, w2l, b2, 1536, 3, 512, 512, 512, 1536);
    mma_gemm<<<dim3(16, 4, BB), 256, SMEMB>>>(a1h, a1l, w2h, w2l, b2, a2h, a2l, ps, pq, T1, T2, 512, 2, 1536, 512, 0);
    statfin1<<<dim3(2, 16), 256>>>(ps, pq, pm, qm, 512);
    statfin2<<<2, 256>>>(pm, qm, m2, i2, 512, (float)BB * (float)T2);

    // L3: fold bn2, offsets {0,3,6}, relu; 3-term; stats fused
    fold_split<<<512, 256>>>(h3w, h3b, m2, i2, bn2g, bn2b, w3h, w3l, b3, 1536, 3, 512, 512, 512, 1536);
    mma_gemm<<<dim3(16, 4, BB), 256, SMEMB>>>(a2h, a2l, w3h, w3l, b3, a3h, a3l, ps, pq, T2, T3, 512, 3, 1536, 512, 0);
    statfin1<<<dim3(2, 16), 256>>>(ps, pq, pm, qm, 512);
    statfin2<<<2, 256>>>(pm, qm, m3, i3, 512, (float)BB * (float)T3);

    // L4: fold bn3, 512->512, relu6; 3-term; stats fused
    fold_split<<<512, 256>>>(h4w, h4b, m3, i3, bn3g, bn3b, w4h, w4l, b4, 512, 1, 512, 512, 512, 512);
    mma_gemm<<<dim3(16, 4, BB), 256, SMEMB>>>(a3h, a3l, w4h, w4l, b4, a4h, a4l, ps, pq, T3, T3, 512, 0, 512, 512, 1);
    statfin1<<<dim3(2, 16), 256>>>(ps, pq, pm, qm, 512);
    statfin2<<<2, 256>>>(pm, qm, m4, i4, 512, (float)BB * (float)T3);

    // L5: fold bn4, 512->1500 (pad 1536), relu6; 2-term (Wl dropped); stats-only
    fold_split<<<C5P, 256>>>(h5w, h5b, m4, i4, bn4g, bn4b, w5h, nullptr, b5, 512, 1, 512, 512, C5, 512);
    mma_gemm<<<dim3(16, 12, BB), 256, SMEMB>>>(a4h, a4l, w5h, nullptr, b5, nullptr, nullptr, p5s, p5q, T3, T5, 512, 0, 512, C5P, 1);

    // stats pooling (bn5 folded analytically)
    part5reduce<<<dim3(6, BB), 256>>>(p5s, p5q, rsum, rsq);
    chstats5<<<6, 256>>>(rsum, rsq, m5, i5);
    pool_kernel<<<(BB * C5 + 255) / 256, 256>>>(rsum, rsq, m5, i5, bn5g, bn5b, pool);

    // tail FCs
    fc_kernel<<<dim3(512, BB), 128>>>(pool, l1w, l1b, z1, 3000, 512);
    bnc_kernel<<<2, 256>>>(z1, bn6g, bn6b, u1, 512);
    fc_kernel<<<dim3(512, BB), 128>>>(u1, l2w, l2b, z2, 512, 512);
    bnc_kernel<<<2, 256>>>(z2, bn7g, bn7b, (float*)d_out, 512);
}

// round 14
// speedup vs baseline: 2.0707x; 1.0505x over previous
#include <cuda_runtime.h>
#include <cuda_fp16.h>
#include <cstdint>
#include <cstddef>

#define EPSF 1e-5f
constexpr int BB = 32, F0 = 20, T0 = 2048;
constexpr int T1 = 2044, T2 = 2040, T3 = 2034, T5 = 2034;
constexpr int C5 = 1500, C5P = 1536;
constexpr int NSL = 512;

// ------------------------------- scratch -----------------------------------
__device__ __align__(16) __half g_xhi[(size_t)BB * T0 * 32],  g_xlo[(size_t)BB * T0 * 32];
__device__ __align__(16) __half g_a1hi[(size_t)BB * T1 * 512], g_a1lo[(size_t)BB * T1 * 512];
__device__ __align__(16) __half g_a2hi[(size_t)BB * T2 * 512], g_a2lo[(size_t)BB * T2 * 512];
__device__ __align__(16) __half g_a3hi[(size_t)BB * T3 * 512], g_a3lo[(size_t)BB * T3 * 512];
__device__ __align__(16) __half g_a4hi[(size_t)BB * T3 * 512], g_a4lo[(size_t)BB * T3 * 512];
__device__ __align__(16) __half g_w1hi[512 * 160],  g_w1lo[512 * 160];
__device__ __align__(16) __half g_w2hi[512 * 1536], g_w2lo[512 * 1536];
__device__ __align__(16) __half g_w3hi[512 * 1536], g_w3lo[512 * 1536];
__device__ __align__(16) __half g_w4hi[512 * 512],  g_w4lo[512 * 512];
__device__ __align__(16) __half g_w5hi[C5P * 512];
__device__ float g_b1p[512], g_b2p[512], g_b3p[512], g_b4p[512], g_b5p[C5P];
__device__ float g_ps[NSL * 512], g_pq[NSL * 512];
__device__ float g_pm[16 * 512], g_qm[16 * 512];
__device__ float g_p5s[16 * BB * C5P], g_p5q[16 * BB * C5P];
__device__ float g_m1[512], g_i1[512], g_m2[512], g_i2[512];
__device__ float g_m3[512], g_i3[512], g_m4[512], g_i4[512];
__device__ float g_m5[C5], g_i5[C5];
__device__ float g_rsum[BB * C5], g_rsq[BB * C5];
__device__ float g_pool[BB * 3000];
__device__ float g_z1[BB * 512], g_u1[BB * 512], g_z2[BB * 512];

// ----------------------------- helpers --------------------------------------
__device__ __forceinline__ uint32_t s2u(const void* p) {
    uint32_t a;
    asm("{ .reg .u64 t; cvta.to.shared.u64 t, %1; cvt.u32.u64 %0, t; }" : "=r"(a) : "l"(p));
    return a;
}
__device__ __forceinline__ void ldm_x4(uint32_t a[4], uint32_t addr) {
    asm volatile("ldmatrix.sync.aligned.m8n8.x4.shared.b16 {%0,%1,%2,%3}, [%4];"
                 : "=r"(a[0]), "=r"(a[1]), "=r"(a[2]), "=r"(a[3]) : "r"(addr));
}
__device__ __forceinline__ void mma16816(float c[4], const uint32_t a[4], const uint32_t b[2]) {
    asm volatile("mma.sync.aligned.m16n8k16.row.col.f32.f16.f16.f32 "
                 "{%0,%1,%2,%3}, {%4,%5,%6,%7}, {%8,%9}, {%0,%1,%2,%3};"
                 : "+f"(c[0]), "+f"(c[1]), "+f"(c[2]), "+f"(c[3])
                 : "r"(a[0]), "r"(a[1]), "r"(a[2]), "r"(a[3]), "r"(b[0]), "r"(b[1]));
}
__device__ __forceinline__ void cpa16(uint32_t dst, const void* src, int sz) {
    asm volatile("cp.async.ca.shared.global [%0], [%1], 16, %2;" :: "r"(dst), "l"(src), "r"(sz));
}
#define CP_COMMIT() asm volatile("cp.async.commit_group;" ::: "memory")
#define CP_WAIT1() asm volatile("cp.async.wait_group 1;" ::: "memory")
#define CP_WAIT0() asm volatile("cp.async.wait_group 0;" ::: "memory")

// ------------------------------ prep kernels --------------------------------
__global__ void xsplit(const float* __restrict__ x, __half* __restrict__ xh, __half* __restrict__ xl) {
    int idx = blockIdx.x * 256 + threadIdx.x;
    if (idx >= BB * T0 * 32) return;
    int f = idx & 31, bt = idx >> 5;
    float v = (f < F0) ? x[(size_t)bt * F0 + f] : 0.f;
    __half h = __float2half(v);
    xh[idx] = h;
    xl[idx] = __float2half(v - __half2float(h));
}

__global__ void fold_split(const float* __restrict__ w, const float* __restrict__ bias,
                           const float* __restrict__ mean, const float* __restrict__ istd,
                           const float* __restrict__ g, const float* __restrict__ be,
                           __half* __restrict__ wh, __half* __restrict__ wl, float* __restrict__ bp,
                           int Korig, int NOFF, int C, int Cpad, int Cout, int Kp) {
    int o = blockIdx.x;
    float part = 0.f;
    for (int k = threadIdx.x; k < Kp; k += 256) {
        int j = k / Cpad, c = k - j * Cpad;
        float wa = 0.f;
        if (o < Cout && c < C) {
            float a = 1.f, d = 0.f;
            if (mean) { a = istd[c] * (g ? g[c] : 1.f); d = (be ? be[c] : 0.f) - mean[c] * a; }
            float wv = w[(size_t)o * Korig + c * NOFF + j];
            wa = wv * a;
            part += wv * d;
        }
        __half h = __float2half(wa);
        wh[(size_t)o * Kp + k] = h;
        if (wl) wl[(size_t)o * Kp + k] = __float2half(wa - __half2float(h));
    }
    __shared__ float sh[256];
    sh[threadIdx.x] = part;
    __syncthreads();
    for (int d2 = 128; d2 > 0; d2 >>= 1) {
        if (threadIdx.x < d2) sh[threadIdx.x] += sh[threadIdx.x + d2];
        __syncthreads();
    }
    if (threadIdx.x == 0) bp[o] = (o < Cout ? bias[o] : 0.f) + sh[0];
}

// -------------------------- mma.sync GEMM -----------------------------------
// CTA 128x128, BK=32, 4 warps (2m x 2n), warp 64x64, fp16 hi/lo.
// Wl != nullptr: 3-term (AhWh + AhWl + AlWh); else 2-term.
// 2-stage cp.async pipeline (2x40960B smem -> 2 CTAs/SM, 128 thr/CTA).
__global__ __launch_bounds__(128, 2)
void mma_gemm(const __half* __restrict__ Ah, const __half* __restrict__ Al,
              const __half* __restrict__ Wh, const __half* __restrict__ Wl,
              const float* __restrict__ bias,
              __half* __restrict__ Oh, __half* __restrict__ Ol,
              float* __restrict__ Ps, float* __restrict__ Pq,
              int Tin, int Tout, int Cpad, int step, int Kp, int Coutp, int act) {
    extern __shared__ char smem[];
    uint32_t su = s2u(smem);
    int tid = threadIdx.x, lane = tid & 31, wid = tid >> 5;
    int b = blockIdx.z, t0 = blockIdx.x * 128, obase = blockIdx.y * 128;
    int wm = wid >> 1, wn = wid & 1;
    int nk = Kp >> 5;
    bool uwl = (Wl != nullptr);

    float acc[4][8][4];
#pragma unroll
    for (int i = 0; i < 4; i++)
#pragma unroll
        for (int j = 0; j < 8; j++)
#pragma unroll
            for (int q = 0; q < 4; q++) acc[i][j][q] = 0.f;

    auto load_stage = [&](int buf, int kc) {
        int kc0 = kc << 5;
        int j = kc0 / Cpad, c0 = kc0 - j * Cpad, off = j * step;
        uint32_t sb = su + buf * 40960;
        const __half* pa[2] = {Ah, Al};
#pragma unroll
        for (int h = 0; h < 2; h++) {
#pragma unroll
            for (int i = 0; i < 4; i++) {
                int e = tid + i * 128, r = e >> 2, c = e & 3;
                cpa16(sb + h * 10240 + r * 80 + c * 16,
                      pa[h] + ((size_t)b * Tin + t0 + off + r) * Cpad + c0 + c * 8,
                      (t0 + r < Tout) ? 16 : 0);
            }
        }
#pragma unroll
        for (int i = 0; i < 4; i++) {
            int e = tid + i * 128, r = e >> 2, c = e & 3;
            cpa16(sb + 20480 + r * 80 + c * 16,
                  Wh + ((size_t)(obase + r)) * Kp + kc0 + c * 8, 16);
        }
        if (uwl) {
#pragma unroll
            for (int i = 0; i < 4; i++) {
                int e = tid + i * 128, r = e >> 2, c = e & 3;
                cpa16(sb + 30720 + r * 80 + c * 16,
                      Wl + ((size_t)(obase + r)) * Kp + kc0 + c * 8, 16);
            }
        }
        CP_COMMIT();
    };

    auto compute = [&](int buf) {
        uint32_t sb = su + buf * 40960;
#pragma unroll
        for (int ks = 0; ks < 2; ks++) {
            uint32_t ah[4][4], al[4][4];
#pragma unroll
            for (int mf = 0; mf < 4; mf++) {
                int row = wm * 64 + mf * 16 + (lane & 15);
                uint32_t addr = sb + row * 80 + (ks * 16 + ((lane >> 4) << 3)) * 2;
                ldm_x4(ah[mf], addr);
                ldm_x4(al[mf], addr + 10240);
            }
#pragma unroll
            for (int nb = 0; nb < 2; nb++) {
                uint32_t bh[4][2], bl[4][2];
#pragma unroll
                for (int qq = 0; qq < 2; qq++) {
                    int g = lane >> 3;
                    int rowb = wn * 64 + nb * 32 + qq * 16 + ((g >> 1) << 3) + (lane & 7);
                    uint32_t addr = sb + 20480 + rowb * 80 + (ks * 16 + ((g & 1) << 3)) * 2;
                    uint32_t th[4];
                    ldm_x4(th, addr);
                    bh[qq * 2][0] = th[0]; bh[qq * 2][1] = th[1];
                    bh[qq * 2 + 1][0] = th[2]; bh[qq * 2 + 1][1] = th[3];
                    if (uwl) {
                        uint32_t tl[4];
                        ldm_x4(tl, addr + 10240);
                        bl[qq * 2][0] = tl[0]; bl[qq * 2][1] = tl[1];
                        bl[qq * 2 + 1][0] = tl[2]; bl[qq * 2 + 1][1] = tl[3];
                    }
                }
#pragma unroll
                for (int mf = 0; mf < 4; mf++)
#pragma unroll
                    for (int q = 0; q < 4; q++) {
                        int nf = nb * 4 + q;
                        mma16816(acc[mf][nf], ah[mf], bh[q]);
                        mma16816(acc[mf][nf], al[mf], bh[q]);
                        if (uwl) mma16816(acc[mf][nf], ah[mf], bl[q]);
                    }
            }
        }
    };

    load_stage(0, 0);
    load_stage(1, 1);
    for (int kc = 0; kc < nk; kc++) {
        if (kc < nk - 2) CP_WAIT1(); else CP_WAIT0();
        __syncthreads();
        compute(kc & 1);
        __syncthreads();
        if (kc + 2 < nk) load_stage(kc & 1, kc + 2);
    }

    // ------- fused epilogue: activations + column stats -------
    int l4 = lane >> 2, l2 = (lane & 3) << 1;
    float s_[8][2] = {}, q_[8][2] = {};
#pragma unroll
    for (int mf = 0; mf < 4; mf++)
#pragma unroll
        for (int hh = 0; hh < 2; hh++) {
            int t = t0 + wm * 64 + mf * 16 + l4 + hh * 8;
            bool tv = t < Tout;
            size_t ro = ((size_t)b * Tout + t) * Coutp + obase + wn * 64;
#pragma unroll
            for (int nf = 0; nf < 8; nf++) {
                int o = nf * 8 + l2;
                float v0 = acc[mf][nf][hh * 2 + 0] + bias[obase + wn * 64 + o];
                float v1 = acc[mf][nf][hh * 2 + 1] + bias[obase + wn * 64 + o + 1];
                v0 = fmaxf(v0, 0.f); v1 = fmaxf(v1, 0.f);
                if (act) { v0 = fminf(v0, 6.f); v1 = fminf(v1, 6.f); }
                if (tv) {
                    s_[nf][0] += v0; q_[nf][0] += v0 * v0;
                    s_[nf][1] += v1; q_[nf][1] += v1 * v1;
                    if (Oh) {
                        __half h0 = __float2half(v0), h1 = __float2half(v1);
                        *(__half2*)(Oh + ro + o) = __halves2half2(h0, h1);
                        *(__half2*)(Ol + ro + o) = __halves2half2(
                            __float2half(v0 - __half2float(h0)), __float2half(v1 - __half2float(h1)));
                    }
                }
            }
        }
    if (Ps) {
#pragma unroll
        for (int nf = 0; nf < 8; nf++)
#pragma unroll
            for (int e = 0; e < 2; e++)
#pragma unroll
                for (int o = 4; o <= 16; o <<= 1) {
                    s_[nf][e] += __shfl_xor_sync(0xffffffffu, s_[nf][e], o);
                    q_[nf][e] += __shfl_xor_sync(0xffffffffu, q_[nf][e], o);
                }
        float* ss = (float*)smem;
        float* sq = ss + 128;
        __syncthreads();
        ss[tid] = 0.f; ss[tid + 128] = 0.f;
        __syncthreads();
        if ((lane >> 2) == 0) {
#pragma unroll
            for (int nf = 0; nf < 8; nf++)
#pragma unroll
                for (int e = 0; e < 2; e++) {
                    int col = wn * 64 + nf * 8 + (lane & 3) * 2 + e;
                    atomicAdd(&ss[col], s_[nf][e]);
                    atomicAdd(&sq[col], q_[nf][e]);
                }
        }
        __syncthreads();
        {
            size_t pidx = ((size_t)blockIdx.x * BB + b) * Coutp + obase + tid;
            Ps[pidx] = ss[tid];
            Pq[pidx] = sq[tid];
        }
    }
}

// --------------------------- stats / tail -----------------------------------
__global__ void statfin1(const float* __restrict__ ps, const float* __restrict__ pq,
                         float* __restrict__ pm, float* __restrict__ qm, int Cpad) {
    int c = blockIdx.x * 256 + threadIdx.x;
    int g = blockIdx.y;
    float s = 0.f, q = 0.f;
    for (int i = g * 32; i < g * 32 + 32; i++) {
        s += ps[(size_t)i * Cpad + c];
        q += pq[(size_t)i * Cpad + c];
    }
    pm[(size_t)g * Cpad + c] = s;
    qm[(size_t)g * Cpad + c] = q;
}
__global__ void statfin2(const float* __restrict__ pm, const float* __restrict__ qm,
                         float* __restrict__ mean, float* __restrict__ istd, int Cpad, float N) {
    int c = blockIdx.x * 256 + threadIdx.x;
    if (c >= Cpad) return;
    float s = 0.f, q = 0.f;
    for (int i = 0; i < 16; i++) { s += pm[(size_t)i * Cpad + c]; q += qm[(size_t)i * Cpad + c]; }
    float m = s / N;
    mean[c] = m;
    istd[c] = rsqrtf(q / N - m * m + EPSF);
}
__global__ void part5reduce(const float* __restrict__ ps, const float* __restrict__ pq,
                            float* __restrict__ rsum, float* __restrict__ rsq) {
    int c = blockIdx.x * 256 + threadIdx.x;
    int b = blockIdx.y;
    if (c >= C5) return;
    float s = 0.f, q = 0.f;
    for (int i = 0; i < 16; i++) {
        s += ps[((size_t)i * BB + b) * C5P + c];
        q += pq[((size_t)i * BB + b) * C5P + c];
    }
    rsum[b * C5 + c] = s;
    rsq[b * C5 + c] = q;
}
__global__ void chstats5(const float* __restrict__ rsum, const float* __restrict__ rsq,
                         float* __restrict__ mean, float* __restrict__ istd) {
    int c = blockIdx.x * 256 + threadIdx.x;
    if (c >= C5) return;
    float s = 0.f, ss = 0.f;
    for (int b = 0; b < BB; b++) { s += rsum[b * C5 + c]; ss += rsq[b * C5 + c]; }
    float N = (float)BB * (float)T5;
    float m = s / N;
    mean[c] = m;
    istd[c] = rsqrtf(ss / N - m * m + EPSF);
}
__global__ void pool_kernel(const float* __restrict__ rsum, const float* __restrict__ rsq,
                            const float* __restrict__ m5, const float* __restrict__ i5,
                            const float* __restrict__ g5, const float* __restrict__ be5,
                            float* __restrict__ pooled) {
    int idx = blockIdx.x * 256 + threadIdx.x;
    if (idx >= BB * C5) return;
    int c = idx % C5, b = idx / C5;
    float Tf = (float)T5;
    float mt = rsum[b * C5 + c] / Tf;
    float vart = (rsq[b * C5 + c] - Tf * mt * mt) / (Tf - 1.f);
    float a = i5[c] * g5[c];
    float d = be5[c] - m5[c] * a;
    pooled[(size_t)b * 3000 + c] = a * mt + d;
    pooled[(size_t)b * 3000 + 1500 + c] = fabsf(a) * sqrtf(fmaxf(vart, 0.f));
}
__global__ void fc_kernel(const float* __restrict__ in, const float* __restrict__ w,
                          const float* __restrict__ bias, float* __restrict__ out, int K, int Cout) {
    int o = blockIdx.x, b = blockIdx.y;
    const float* ir = in + (size_t)b * K;
    const float* wr = w + (size_t)o * K;
    float s = 0.f;
    for (int k = threadIdx.x; k < K; k += 128) s += ir[k] * wr[k];
    __shared__ float sh[128];
    sh[threadIdx.x] = s;
    __syncthreads();
    for (int d = 64; d > 0; d >>= 1) {
        if (threadIdx.x < d) sh[threadIdx.x] += sh[threadIdx.x + d];
        __syncthreads();
    }
    if (threadIdx.x == 0) out[(size_t)b * Cout + o] = fminf(fmaxf(sh[0] + bias[o], 0.f), 6.f);
}
__global__ void bnc_kernel(const float* __restrict__ z, const float* __restrict__ g,
                           const float* __restrict__ be, float* __restrict__ out, int C) {
    int c = threadIdx.x + blockIdx.x * 256;
    if (c >= C) return;
    float s = 0.f, ss = 0.f;
    for (int b = 0; b < BB; b++) { float v = z[(size_t)b * C + c]; s += v; ss += v * v; }
    float m = s / (float)BB;
    float is = rsqrtf(ss / (float)BB - m * m + EPSF);
    for (int b = 0; b < BB; b++)
        out[(size_t)b * C + c] = (z[(size_t)b * C + c] - m) * is * g[c] + be[c];
}

// ------------------------------- host ---------------------------------------
static void* sa(const void* sym) { void* p = nullptr; cudaGetSymbolAddress(&p, sym); return p; }

extern "C" void kernel_launch(void* const* d_in, const int* in_sizes, int n_in,
                              void* d_out, int out_size) {
    const float* x = (const float*)d_in[0];
    const float *h1w = (const float*)d_in[1], *h1b = (const float*)d_in[2];
    const float *h2w = (const float*)d_in[3], *h2b = (const float*)d_in[4];
    const float *bn2g = (const float*)d_in[5], *bn2b = (const float*)d_in[6];
    const float *h3w = (const float*)d_in[7], *h3b = (const float*)d_in[8];
    const float *bn3g = (const float*)d_in[9], *bn3b = (const float*)d_in[10];
    const float *h4w = (const float*)d_in[11], *h4b = (const float*)d_in[12];
    const float *bn4g = (const float*)d_in[13], *bn4b = (const float*)d_in[14];
    const float *h5w = (const float*)d_in[15], *h5b = (const float*)d_in[16];
    const float *bn5g = (const float*)d_in[17], *bn5b = (const float*)d_in[18];
    const float *l1w = (const float*)d_in[19], *l1b = (const float*)d_in[20];
    const float *bn6g = (const float*)d_in[21], *bn6b = (const float*)d_in[22];
    const float *l2w = (const float*)d_in[23], *l2b = (const float*)d_in[24];
    const float *bn7g = (const float*)d_in[25], *bn7b = (const float*)d_in[26];

    __half *xh = (__half*)sa(g_xhi), *xl = (__half*)sa(g_xlo);
    __half *a1h = (__half*)sa(g_a1hi), *a1l = (__half*)sa(g_a1lo);
    __half *a2h = (__half*)sa(g_a2hi), *a2l = (__half*)sa(g_a2lo);
    __half *a3h = (__half*)sa(g_a3hi), *a3l = (__half*)sa(g_a3lo);
    __half *a4h = (__half*)sa(g_a4hi), *a4l = (__half*)sa(g_a4lo);
    __half *w1h = (__half*)sa(g_w1hi), *w1l = (__half*)sa(g_w1lo);
    __half *w2h = (__half*)sa(g_w2hi), *w2l = (__half*)sa(g_w2lo);
    __half *w3h = (__half*)sa(g_w3hi), *w3l = (__half*)sa(g_w3lo);
    __half *w4h = (__half*)sa(g_w4hi), *w4l = (__half*)sa(g_w4lo);
    __half *w5h = (__half*)sa(g_w5hi);
    float *b1 = (float*)sa(g_b1p), *b2 = (float*)sa(g_b2p), *b3 = (float*)sa(g_b3p);
    float *b4 = (float*)sa(g_b4p), *b5 = (float*)sa(g_b5p);
    float *ps = (float*)sa(g_ps), *pq = (float*)sa(g_pq);
    float *pm = (float*)sa(g_pm), *qm = (float*)sa(g_qm);
    float *p5s = (float*)sa(g_p5s), *p5q = (float*)sa(g_p5q);
    float *m1 = (float*)sa(g_m1), *i1 = (float*)sa(g_i1), *m2 = (float*)sa(g_m2), *i2 = (float*)sa(g_i2);
    float *m3 = (float*)sa(g_m3), *i3 = (float*)sa(g_i3), *m4 = (float*)sa(g_m4), *i4 = (float*)sa(g_i4);
    float *m5 = (float*)sa(g_m5), *i5 = (float*)sa(g_i5);
    float *rsum = (float*)sa(g_rsum), *rsq = (float*)sa(g_rsq), *pool = (float*)sa(g_pool);
    float *z1 = (float*)sa(g_z1), *u1 = (float*)sa(g_u1), *z2 = (float*)sa(g_z2);

    const int SMEMB = 2 * 40960;
    cudaFuncSetAttribute(mma_gemm, cudaFuncAttributeMaxDynamicSharedMemorySize, SMEMB);

    xsplit<<<(BB * T0 * 32 + 255) / 256, 256>>>(x, xh, xl);

    // L1: K'=160 (5 offset blocks, Cpad=32), step 1, relu; 3-term; stats fused
    fold_split<<<512, 256>>>(h1w, h1b, nullptr, nullptr, nullptr, nullptr, w1h, w1l, b1, 100, 5, 20, 32, 512, 160);
    mma_gemm<<<dim3(16, 4, BB), 128, SMEMB>>>(xh, xl, w1h, w1l, b1, a1h, a1l, ps, pq, T0, T1, 32, 1, 160, 512, 0);
    statfin1<<<dim3(2, 16), 256>>>(ps, pq, pm, qm, 512);
    statfin2<<<2, 256>>>(pm, qm, m1, i1, 512, (float)BB * (float)T1);

    // L2: fold bn1, offsets {0,2,4}, relu; 3-term; stats fused
    fold_split<<<512, 256>>>(h2w, h2b, m1, i1, nullptr, nullptr, w2h, w2l, b2, 1536, 3, 512, 512, 512, 1536);
    mma_gemm<<<dim3(16, 4, BB), 128, SMEMB>>>(a1h, a1l, w2h, w2l, b2, a2h, a2l, ps, pq, T1, T2, 512, 2, 1536, 512, 0);
    statfin1<<<dim3(2, 16), 256>>>(ps, pq, pm, qm, 512);
    statfin2<<<2, 256>>>(pm, qm, m2, i2, 512, (float)BB * (float)T2);

    // L3: fold bn2, offsets {0,3,6}, relu; 3-term; stats fused
    fold_split<<<512, 256>>>(h3w, h3b, m2, i2, bn2g, bn2b, w3h, w3l, b3, 1536, 3, 512, 512, 512, 1536);
    mma_gemm<<<dim3(16, 4, BB), 128, SMEMB>>>(a2h, a2l, w3h, w3l, b3, a3h, a3l, ps, pq, T2, T3, 512, 3, 1536, 512, 0);
    statfin1<<<dim3(2, 16), 256>>>(ps, pq, pm, qm, 512);
    statfin2<<<2, 256>>>(pm, qm, m3, i3, 512, (float)BB * (float)T3);

    // L4: fold bn3, 512->512, relu6; 3-term; stats fused
    fold_split<<<512, 256>>>(h4w, h4b, m3, i3, bn3g, bn3b, w4h, w4l, b4, 512, 1, 512, 512, 512, 512);
    mma_gemm<<<dim3(16, 4, BB), 128, SMEMB>>>(a3h, a3l, w4h, w4l, b4, a4h, a4l, ps, pq, T3, T3, 512, 0, 512, 512, 1);
    statfin1<<<dim3(2, 16), 256>>>(ps, pq, pm, qm, 512);
    statfin2<<<2, 256>>>(pm, qm, m4, i4, 512, (float)BB * (float)T3);

    // L5: fold bn4, 512->1500 (pad 1536), relu6; 2-term (Wl dropped); stats-only
    fold_split<<<C5P, 256>>>(h5w, h5b, m4, i4, bn4g, bn4b, w5h, nullptr, b5, 512, 1, 512, 512, C5, 512);
    mma_gemm<<<dim3(16, 12, BB), 128, SMEMB>>>(a4h, a4l, w5h, nullptr, b5, nullptr, nullptr, p5s, p5q, T3, T5, 512, 0, 512, C5P, 1);

    // stats pooling (bn5 folded analytically)
    part5reduce<<<dim3(6, BB), 256>>>(p5s, p5q, rsum, rsq);
    chstats5<<<6, 256>>>(rsum, rsq, m5, i5);
    pool_kernel<<<(BB * C5 + 255) / 256, 256>>>(rsum, rsq, m5, i5, bn5g, bn5b, pool);

    // tail FCs
    fc_kernel<<<dim3(512, BB), 128>>>(pool, l1w, l1b, z1, 3000, 512);
    bnc_kernel<<<2, 256>>>(z1, bn6g, bn6b, u1, 512);
    fc_kernel<<<dim3(512, BB), 128>>>(u1, l2w, l2b, z2, 512, 512);
    bnc_kernel<<<2, 256>>>(z2, bn7g, bn7b, (float*)d_out, 512);
}

// round 15
// speedup vs baseline: 2.1033x; 1.0157x over previous
#include <cuda_runtime.h>
#include <cuda_fp16.h>
#include <cstdint>
#include <cstddef>

#define EPSF 1e-5f
constexpr int BB = 32, F0 = 20, T0 = 2048;
constexpr int T1 = 2044, T2 = 2040, T3 = 2034, T5 = 2034;
constexpr int C5 = 1500, C5P = 1536;
constexpr int NSL = 512;

// ------------------------------- scratch -----------------------------------
__device__ __align__(16) __half g_xhi[(size_t)BB * T0 * 32],  g_xlo[(size_t)BB * T0 * 32];
__device__ __align__(16) __half g_a1hi[(size_t)BB * T1 * 512], g_a1lo[(size_t)BB * T1 * 512];
__device__ __align__(16) __half g_a2hi[(size_t)BB * T2 * 512], g_a2lo[(size_t)BB * T2 * 512];
__device__ __align__(16) __half g_a3hi[(size_t)BB * T3 * 512], g_a3lo[(size_t)BB * T3 * 512];
__device__ __align__(16) __half g_a4hi[(size_t)BB * T3 * 512], g_a4lo[(size_t)BB * T3 * 512];
__device__ __align__(16) __half g_w1hi[512 * 160],  g_w1lo[512 * 160];
__device__ __align__(16) __half g_w2hi[512 * 1536], g_w2lo[512 * 1536];
__device__ __align__(16) __half g_w3hi[512 * 1536], g_w3lo[512 * 1536];
__device__ __align__(16) __half g_w4hi[512 * 512],  g_w4lo[512 * 512];
__device__ __align__(16) __half g_w5hi[C5P * 512];
__device__ float g_b1p[512], g_b2p[512], g_b3p[512], g_b4p[512], g_b5p[C5P];
__device__ float g_ps[NSL * 512], g_pq[NSL * 512];
__device__ float g_p5s[16 * BB * C5P], g_p5q[16 * BB * C5P];
__device__ float g_m1[512], g_i1[512], g_m2[512], g_i2[512];
__device__ float g_m3[512], g_i3[512], g_m4[512], g_i4[512];
__device__ float g_rsum[BB * C5], g_rsq[BB * C5];
__device__ float g_pool[BB * 3000];
__device__ float g_z1[BB * 512], g_u1[BB * 512], g_z2[BB * 512];

// ----------------------------- helpers --------------------------------------
__device__ __forceinline__ uint32_t s2u(const void* p) {
    uint32_t a;
    asm("{ .reg .u64 t; cvta.to.shared.u64 t, %1; cvt.u32.u64 %0, t; }" : "=r"(a) : "l"(p));
    return a;
}
__device__ __forceinline__ void ldm_x4(uint32_t a[4], uint32_t addr) {
    asm volatile("ldmatrix.sync.aligned.m8n8.x4.shared.b16 {%0,%1,%2,%3}, [%4];"
                 : "=r"(a[0]), "=r"(a[1]), "=r"(a[2]), "=r"(a[3]) : "r"(addr));
}
__device__ __forceinline__ void mma16816(float c[4], const uint32_t a[4], const uint32_t b[2]) {
    asm volatile("mma.sync.aligned.m16n8k16.row.col.f32.f16.f16.f32 "
                 "{%0,%1,%2,%3}, {%4,%5,%6,%7}, {%8,%9}, {%0,%1,%2,%3};"
                 : "+f"(c[0]), "+f"(c[1]), "+f"(c[2]), "+f"(c[3])
                 : "r"(a[0]), "r"(a[1]), "r"(a[2]), "r"(a[3]), "r"(b[0]), "r"(b[1]));
}
__device__ __forceinline__ void cpa16(uint32_t dst, const void* src, int sz) {
    asm volatile("cp.async.ca.shared.global [%0], [%1], 16, %2;" :: "r"(dst), "l"(src), "r"(sz));
}
__device__ __forceinline__ void cpa16cg(uint32_t dst, const void* src) {
    asm volatile("cp.async.cg.shared.global [%0], [%1], 16;" :: "r"(dst), "l"(src));
}
#define CP_COMMIT() asm volatile("cp.async.commit_group;" ::: "memory")
#define CP_WAIT1() asm volatile("cp.async.wait_group 1;" ::: "memory")
#define CP_WAIT0() asm volatile("cp.async.wait_group 0;" ::: "memory")

// ------------------------------ prep kernels --------------------------------
__global__ void xsplit(const float* __restrict__ x, __half* __restrict__ xh, __half* __restrict__ xl) {
    int idx = blockIdx.x * 256 + threadIdx.x;
    if (idx >= BB * T0 * 32) return;
    int f = idx & 31, bt = idx >> 5;
    float v = (f < F0) ? x[(size_t)bt * F0 + f] : 0.f;
    __half h = __float2half(v);
    xh[idx] = h;
    xl[idx] = __float2half(v - __half2float(h));
}

__global__ void fold_split(const float* __restrict__ w, const float* __restrict__ bias,
                           const float* __restrict__ mean, const float* __restrict__ istd,
                           const float* __restrict__ g, const float* __restrict__ be,
                           __half* __restrict__ wh, __half* __restrict__ wl, float* __restrict__ bp,
                           int Korig, int NOFF, int C, int Cpad, int Cout, int Kp) {
    int o = blockIdx.x;
    float part = 0.f;
    for (int k = threadIdx.x; k < Kp; k += 256) {
        int j = k / Cpad, c = k - j * Cpad;
        float wa = 0.f;
        if (o < Cout && c < C) {
            float a = 1.f, d = 0.f;
            if (mean) { a = istd[c] * (g ? g[c] : 1.f); d = (be ? be[c] : 0.f) - mean[c] * a; }
            float wv = w[(size_t)o * Korig + c * NOFF + j];
            wa = wv * a;
            part += wv * d;
        }
        __half h = __float2half(wa);
        wh[(size_t)o * Kp + k] = h;
        if (wl) wl[(size_t)o * Kp + k] = __float2half(wa - __half2float(h));
    }
    __shared__ float sh[256];
    sh[threadIdx.x] = part;
    __syncthreads();
    for (int d2 = 128; d2 > 0; d2 >>= 1) {
        if (threadIdx.x < d2) sh[threadIdx.x] += sh[threadIdx.x + d2];
        __syncthreads();
    }
    if (threadIdx.x == 0) bp[o] = (o < Cout ? bias[o] : 0.f) + sh[0];
}

// -------------------------- mma.sync GEMM -----------------------------------
// CTA 128x128, BK=32, 4 warps (2m x 2n), warp 64x64, fp16 hi/lo.
// Wl != nullptr: 3-term; else 2-term. 2-stage cp.async pipeline.
__global__ __launch_bounds__(128, 2)
void mma_gemm(const __half* __restrict__ Ah, const __half* __restrict__ Al,
              const __half* __restrict__ Wh, const __half* __restrict__ Wl,
              const float* __restrict__ bias,
              __half* __restrict__ Oh, __half* __restrict__ Ol,
              float* __restrict__ Ps, float* __restrict__ Pq,
              int Tin, int Tout, int Cpad, int step, int Kp, int Coutp, int act) {
    extern __shared__ char smem[];
    uint32_t su = s2u(smem);
    int tid = threadIdx.x, lane = tid & 31, wid = tid >> 5;
    int b = blockIdx.z, t0 = blockIdx.x * 128, obase = blockIdx.y * 128;
    int wm = wid >> 1, wn = wid & 1;
    int nk = Kp >> 5;
    bool uwl = (Wl != nullptr);

    float acc[4][8][4];
#pragma unroll
    for (int i = 0; i < 4; i++)
#pragma unroll
        for (int j = 0; j < 8; j++)
#pragma unroll
            for (int q = 0; q < 4; q++) acc[i][j][q] = 0.f;

    auto load_stage = [&](int buf, int kc) {
        int kc0 = kc << 5;
        int j = kc0 / Cpad, c0 = kc0 - j * Cpad, off = j * step;
        uint32_t sb = su + buf * 40960;
        const __half* pa[2] = {Ah, Al};
#pragma unroll
        for (int h = 0; h < 2; h++) {
#pragma unroll
            for (int i = 0; i < 4; i++) {
                int e = tid + i * 128, r = e >> 2, c = e & 3;
                cpa16(sb + h * 10240 + r * 80 + c * 16,
                      pa[h] + ((size_t)b * Tin + t0 + off + r) * Cpad + c0 + c * 8,
                      (t0 + r < Tout) ? 16 : 0);
            }
        }
#pragma unroll
        for (int i = 0; i < 4; i++) {
            int e = tid + i * 128, r = e >> 2, c = e & 3;
            cpa16cg(sb + 20480 + r * 80 + c * 16,
                    Wh + ((size_t)(obase + r)) * Kp + kc0 + c * 8);
        }
        if (uwl) {
#pragma unroll
            for (int i = 0; i < 4; i++) {
                int e = tid + i * 128, r = e >> 2, c = e & 3;
                cpa16cg(sb + 30720 + r * 80 + c * 16,
                        Wl + ((size_t)(obase + r)) * Kp + kc0 + c * 8);
            }
        }
        CP_COMMIT();
    };

    auto compute = [&](int buf) {
        uint32_t sb = su + buf * 40960;
#pragma unroll
        for (int ks = 0; ks < 2; ks++) {
            uint32_t ah[4][4], al[4][4];
#pragma unroll
            for (int mf = 0; mf < 4; mf++) {
                int row = wm * 64 + mf * 16 + (lane & 15);
                uint32_t addr = sb + row * 80 + (ks * 16 + ((lane >> 4) << 3)) * 2;
                ldm_x4(ah[mf], addr);
                ldm_x4(al[mf], addr + 10240);
            }
#pragma unroll
            for (int nb = 0; nb < 2; nb++) {
                uint32_t bh[4][2], bl[4][2];
#pragma unroll
                for (int qq = 0; qq < 2; qq++) {
                    int g = lane >> 3;
                    int rowb = wn * 64 + nb * 32 + qq * 16 + ((g >> 1) << 3) + (lane & 7);
                    uint32_t addr = sb + 20480 + rowb * 80 + (ks * 16 + ((g & 1) << 3)) * 2;
                    uint32_t th[4];
                    ldm_x4(th, addr);
                    bh[qq * 2][0] = th[0]; bh[qq * 2][1] = th[1];
                    bh[qq * 2 + 1][0] = th[2]; bh[qq * 2 + 1][1] = th[3];
                    if (uwl) {
                        uint32_t tl[4];
                        ldm_x4(tl, addr + 10240);
                        bl[qq * 2][0] = tl[0]; bl[qq * 2][1] = tl[1];
                        bl[qq * 2 + 1][0] = tl[2]; bl[qq * 2 + 1][1] = tl[3];
                    }
                }
#pragma unroll
                for (int mf = 0; mf < 4; mf++)
#pragma unroll
                    for (int q = 0; q < 4; q++) {
                        int nf = nb * 4 + q;
                        mma16816(acc[mf][nf], ah[mf], bh[q]);
                        mma16816(acc[mf][nf], al[mf], bh[q]);
                        if (uwl) mma16816(acc[mf][nf], ah[mf], bl[q]);
                    }
            }
        }
    };

    load_stage(0, 0);
    load_stage(1, 1);
    for (int kc = 0; kc < nk; kc++) {
        if (kc < nk - 2) CP_WAIT1(); else CP_WAIT0();
        __syncthreads();
        compute(kc & 1);
        __syncthreads();
        if (kc + 2 < nk) load_stage(kc & 1, kc + 2);
    }

    // ------- fused epilogue: activations + column stats -------
    int l4 = lane >> 2, l2 = (lane & 3) << 1;
    float s_[8][2] = {}, q_[8][2] = {};
#pragma unroll
    for (int mf = 0; mf < 4; mf++)
#pragma unroll
        for (int hh = 0; hh < 2; hh++) {
            int t = t0 + wm * 64 + mf * 16 + l4 + hh * 8;
            bool tv = t < Tout;
            size_t ro = ((size_t)b * Tout + t) * Coutp + obase + wn * 64;
#pragma unroll
            for (int nf = 0; nf < 8; nf++) {
                int o = nf * 8 + l2;
                float v0 = acc[mf][nf][hh * 2 + 0] + bias[obase + wn * 64 + o];
                float v1 = acc[mf][nf][hh * 2 + 1] + bias[obase + wn * 64 + o + 1];
                v0 = fmaxf(v0, 0.f); v1 = fmaxf(v1, 0.f);
                if (act) { v0 = fminf(v0, 6.f); v1 = fminf(v1, 6.f); }
                if (tv) {
                    s_[nf][0] += v0; q_[nf][0] += v0 * v0;
                    s_[nf][1] += v1; q_[nf][1] += v1 * v1;
                    if (Oh) {
                        __half h0 = __float2half(v0), h1 = __float2half(v1);
                        *(__half2*)(Oh + ro + o) = __halves2half2(h0, h1);
                        *(__half2*)(Ol + ro + o) = __halves2half2(
                            __float2half(v0 - __half2float(h0)), __float2half(v1 - __half2float(h1)));
                    }
                }
            }
        }
    if (Ps) {
#pragma unroll
        for (int nf = 0; nf < 8; nf++)
#pragma unroll
            for (int e = 0; e < 2; e++)
#pragma unroll
                for (int o = 4; o <= 16; o <<= 1) {
                    s_[nf][e] += __shfl_xor_sync(0xffffffffu, s_[nf][e], o);
                    q_[nf][e] += __shfl_xor_sync(0xffffffffu, q_[nf][e], o);
                }
        float* ss = (float*)smem;
        float* sq = ss + 128;
        __syncthreads();
        ss[tid] = 0.f; ss[tid + 128] = 0.f;
        __syncthreads();
        if ((lane >> 2) == 0) {
#pragma unroll
            for (int nf = 0; nf < 8; nf++)
#pragma unroll
                for (int e = 0; e < 2; e++) {
                    int col = wn * 64 + nf * 8 + (lane & 3) * 2 + e;
                    atomicAdd(&ss[col], s_[nf][e]);
                    atomicAdd(&sq[col], q_[nf][e]);
                }
        }
        __syncthreads();
        {
            size_t pidx = ((size_t)blockIdx.x * BB + b) * Coutp + obase + tid;
            Ps[pidx] = ss[tid];
            Pq[pidx] = sq[tid];
        }
    }
}

// --------------------------- stats / tail -----------------------------------
// single-launch reduce of NSL=512 slices: grid 32, block 256.
// thread t handles channel c = bid*16 + (t&15), slice group t>>4 (32 slices).
__global__ void statfin(const float* __restrict__ ps, const float* __restrict__ pq,
                        float* __restrict__ mean, float* __restrict__ istd, int Cpad, float N) {
    __shared__ float shs[256], shq[256];
    int t = threadIdx.x;
    int c = blockIdx.x * 16 + (t & 15);
    int g = t >> 4;
    float s = 0.f, q = 0.f;
    for (int i = g * 32; i < g * 32 + 32; i++) {
        s += ps[(size_t)i * Cpad + c];
        q += pq[(size_t)i * Cpad + c];
    }
    shs[t] = s; shq[t] = q;
    __syncthreads();
    for (int d = 8; d > 0; d >>= 1) {
        if (g < d) { shs[t] += shs[t + d * 16]; shq[t] += shq[t + d * 16]; }
        __syncthreads();
    }
    if (g == 0) {
        float m = shs[t] / N;
        mean[c] = m;
        istd[c] = rsqrtf(shq[t] / N - m * m + EPSF);
    }
}
__global__ void part5reduce(const float* __restrict__ ps, const float* __restrict__ pq,
                            float* __restrict__ rsum, float* __restrict__ rsq) {
    int c = blockIdx.x * 256 + threadIdx.x;
    int b = blockIdx.y;
    if (c >= C5) return;
    float s = 0.f, q = 0.f;
    for (int i = 0; i < 16; i++) {
        s += ps[((size_t)i * BB + b) * C5P + c];
        q += pq[((size_t)i * BB + b) * C5P + c];
    }
    rsum[b * C5 + c] = s;
    rsq[b * C5 + c] = q;
}
// fused bn5 channel stats + stats pooling
__global__ void pool_merged(const float* __restrict__ rsum, const float* __restrict__ rsq,
                            const float* __restrict__ g5, const float* __restrict__ be5,
                            float* __restrict__ pooled) {
    int c = blockIdx.x * 256 + threadIdx.x;
    if (c >= C5) return;
    float s = 0.f, ss = 0.f;
    for (int b = 0; b < BB; b++) { s += rsum[b * C5 + c]; ss += rsq[b * C5 + c]; }
    float N = (float)BB * (float)T5;
    float m5 = s / N;
    float i5 = rsqrtf(ss / N - m5 * m5 + EPSF);
    float a = i5 * g5[c];
    float d = be5[c] - m5 * a;
    float Tf = (float)T5;
    for (int b = 0; b < BB; b++) {
        float mt = rsum[b * C5 + c] / Tf;
        float vart = (rsq[b * C5 + c] - Tf * mt * mt) / (Tf - 1.f);
        pooled[(size_t)b * 3000 + c] = a * mt + d;
        pooled[(size_t)b * 3000 + 1500 + c] = fabsf(a) * sqrtf(fmaxf(vart, 0.f));
    }
}
__global__ void fc_kernel(const float* __restrict__ in, const float* __restrict__ w,
                          const float* __restrict__ bias, float* __restrict__ out, int K, int Cout) {
    int o = blockIdx.x, b = blockIdx.y;
    const float* ir = in + (size_t)b * K;
    const float* wr = w + (size_t)o * K;
    float s = 0.f;
    for (int k = threadIdx.x; k < K; k += 128) s += ir[k] * wr[k];
    __shared__ float sh[128];
    sh[threadIdx.x] = s;
    __syncthreads();
    for (int d = 64; d > 0; d >>= 1) {
        if (threadIdx.x < d) sh[threadIdx.x] += sh[threadIdx.x + d];
        __syncthreads();
    }
    if (threadIdx.x == 0) out[(size_t)b * Cout + o] = fminf(fmaxf(sh[0] + bias[o], 0.f), 6.f);
}
__global__ void bnc_kernel(const float* __restrict__ z, const float* __restrict__ g,
                           const float* __restrict__ be, float* __restrict__ out, int C) {
    int c = threadIdx.x + blockIdx.x * 256;
    if (c >= C) return;
    float s = 0.f, ss = 0.f;
    for (int b = 0; b < BB; b++) { float v = z[(size_t)b * C + c]; s += v; ss += v * v; }
    float m = s / (float)BB;
    float is = rsqrtf(ss / (float)BB - m * m + EPSF);
    for (int b = 0; b < BB; b++)
        out[(size_t)b * C + c] = (z[(size_t)b * C + c] - m) * is * g[c] + be[c];
}

// ------------------------------- host ---------------------------------------
static void* sa(const void* sym) { void* p = nullptr; cudaGetSymbolAddress(&p, sym); return p; }

extern "C" void kernel_launch(void* const* d_in, const int* in_sizes, int n_in,
                              void* d_out, int out_size) {
    const float* x = (const float*)d_in[0];
    const float *h1w = (const float*)d_in[1], *h1b = (const float*)d_in[2];
    const float *h2w = (const float*)d_in[3], *h2b = (const float*)d_in[4];
    const float *bn2g = (const float*)d_in[5], *bn2b = (const float*)d_in[6];
    const float *h3w = (const float*)d_in[7], *h3b = (const float*)d_in[8];
    const float *bn3g = (const float*)d_in[9], *bn3b = (const float*)d_in[10];
    const float *h4w = (const float*)d_in[11], *h4b = (const float*)d_in[12];
    const float *bn4g = (const float*)d_in[13], *bn4b = (const float*)d_in[14];
    const float *h5w = (const float*)d_in[15], *h5b = (const float*)d_in[16];
    const float *bn5g = (const float*)d_in[17], *bn5b = (const float*)d_in[18];
    const float *l1w = (const float*)d_in[19], *l1b = (const float*)d_in[20];
    const float *bn6g = (const float*)d_in[21], *bn6b = (const float*)d_in[22];
    const float *l2w = (const float*)d_in[23], *l2b = (const float*)d_in[24];
    const float *bn7g = (const float*)d_in[25], *bn7b = (const float*)d_in[26];

    __half *xh = (__half*)sa(g_xhi), *xl = (__half*)sa(g_xlo);
    __half *a1h = (__half*)sa(g_a1hi), *a1l = (__half*)sa(g_a1lo);
    __half *a2h = (__half*)sa(g_a2hi), *a2l = (__half*)sa(g_a2lo);
    __half *a3h = (__half*)sa(g_a3hi), *a3l = (__half*)sa(g_a3lo);
    __half *a4h = (__half*)sa(g_a4hi), *a4l = (__half*)sa(g_a4lo);
    __half *w1h = (__half*)sa(g_w1hi), *w1l = (__half*)sa(g_w1lo);
    __half *w2h = (__half*)sa(g_w2hi), *w2l = (__half*)sa(g_w2lo);
    __half *w3h = (__half*)sa(g_w3hi), *w3l = (__half*)sa(g_w3lo);
    __half *w4h = (__half*)sa(g_w4hi), *w4l = (__half*)sa(g_w4lo);
    __half *w5h = (__half*)sa(g_w5hi);
    float *b1 = (float*)sa(g_b1p), *b2 = (float*)sa(g_b2p), *b3 = (float*)sa(g_b3p);
    float *b4 = (float*)sa(g_b4p), *b5 = (float*)sa(g_b5p);
    float *ps = (float*)sa(g_ps), *pq = (float*)sa(g_pq);
    float *p5s = (float*)sa(g_p5s), *p5q = (float*)sa(g_p5q);
    float *m1 = (float*)sa(g_m1), *i1 = (float*)sa(g_i1), *m2 = (float*)sa(g_m2), *i2 = (float*)sa(g_i2);
    float *m3 = (float*)sa(g_m3), *i3 = (float*)sa(g_i3), *m4 = (float*)sa(g_m4), *i4 = (float*)sa(g_i4);
    float *rsum = (float*)sa(g_rsum), *rsq = (float*)sa(g_rsq), *pool = (float*)sa(g_pool);
    float *z1 = (float*)sa(g_z1), *u1 = (float*)sa(g_u1), *z2 = (float*)sa(g_z2);

    const int SMEMB = 2 * 40960;
    cudaFuncSetAttribute(mma_gemm, cudaFuncAttributeMaxDynamicSharedMemorySize, SMEMB);

    xsplit<<<(BB * T0 * 32 + 255) / 256, 256>>>(x, xh, xl);

    // L1: K'=160, step 1, relu; 3-term; stats fused
    fold_split<<<512, 256>>>(h1w, h1b, nullptr, nullptr, nullptr, nullptr, w1h, w1l, b1, 100, 5, 20, 32, 512, 160);
    mma_gemm<<<dim3(16, 4, BB), 128, SMEMB>>>(xh, xl, w1h, w1l, b1, a1h, a1l, ps, pq, T0, T1, 32, 1, 160, 512, 0);
    statfin<<<32, 256>>>(ps, pq, m1, i1, 512, (float)BB * (float)T1);

    // L2: fold bn1, offsets {0,2,4}, relu; 3-term; stats fused
    fold_split<<<512, 256>>>(h2w, h2b, m1, i1, nullptr, nullptr, w2h, w2l, b2, 1536, 3, 512, 512, 512, 1536);
    mma_gemm<<<dim3(16, 4, BB), 128, SMEMB>>>(a1h, a1l, w2h, w2l, b2, a2h, a2l, ps, pq, T1, T2, 512, 2, 1536, 512, 0);
    statfin<<<32, 256>>>(ps, pq, m2, i2, 512, (float)BB * (float)T2);

    // L3: fold bn2, offsets {0,3,6}, relu; 3-term; stats fused
    fold_split<<<512, 256>>>(h3w, h3b, m2, i2, bn2g, bn2b, w3h, w3l, b3, 1536, 3, 512, 512, 512, 1536);
    mma_gemm<<<dim3(16, 4, BB), 128, SMEMB>>>(a2h, a2l, w3h, w3l, b3, a3h, a3l, ps, pq, T2, T3, 512, 3, 1536, 512, 0);
    statfin<<<32, 256>>>(ps, pq, m3, i3, 512, (float)BB * (float)T3);

    // L4: fold bn3, 512->512, relu6; 3-term; stats fused
    fold_split<<<512, 256>>>(h4w, h4b, m3, i3, bn3g, bn3b, w4h, w4l, b4, 512, 1, 512, 512, 512, 512);
    mma_gemm<<<dim3(16, 4, BB), 128, SMEMB>>>(a3h, a3l, w4h, w4l, b4, a4h, a4l, ps, pq, T3, T3, 512, 0, 512, 512, 1);
    statfin<<<32, 256>>>(ps, pq, m4, i4, 512, (float)BB * (float)T3);

    // L5: fold bn4, 512->1500 (pad 1536), relu6; 2-term; stats-only epilogue
    fold_split<<<C5P, 256>>>(h5w, h5b, m4, i4, bn4g, bn4b, w5h, nullptr, b5, 512, 1, 512, 512, C5, 512);
    mma_gemm<<<dim3(16, 12, BB), 128, SMEMB>>>(a4h, a4l, w5h, nullptr, b5, nullptr, nullptr, p5s, p5q, T3, T5, 512, 0, 512, C5P, 1);

    // stats pooling (bn5 folded analytically)
    part5reduce<<<dim3(6, BB), 256>>>(p5s, p5q, rsum, rsq);
    pool_merged<<<6, 256>>>(rsum, rsq, bn5g, bn5b, pool);

    // tail FCs
    fc_kernel<<<dim3(512, BB), 128>>>(pool, l1w, l1b, z1, 3000, 512);
    bnc_kernel<<<2, 256>>>(z1, bn6g, bn6b, u1, 512);
    fc_kernel<<<dim3(512, BB), 128>>>(u1, l2w, l2b, z2, 512, 512);
    bnc_kernel<<<2, 256>>>(z2, bn7g, bn7b, (float*)d_out, 512);
}